// round 10
// baseline (speedup 1.0000x reference)
#include <cuda_runtime.h>
#include <math.h>
#include <stdint.h>

// ---------------------------------------------------------------------------
// LinearAutoregressiveHMM — round 10 (resubmit of r9 after broker failure):
//  * gemm_elp: 3-stage cp.async pipeline, ONE __syncthreads per K-chunk
//    (end-of-iter sync), A panel shrunk to rows 32..127 (zero-skip makes
//    rows <49 unreachable) -> 3 stages still fit 2 CTAs/SM.
//  * pred_em/pred_rec: single-sync per chunk (same overlap, half barriers).
//  * zero-skip + pred decomposition kept from r8.
// ---------------------------------------------------------------------------

#define K_ST   8
#define LSEQ   64
#define CDIM   64
#define BATCH  512
#define PRED   16
#define FDIM   4096
#define AST    68            // smem row stride (floats)
#define PST    68

// static scratch
__device__ float d_Wn  [K_ST * CDIM * FDIM];   // tf32(-(IC@W))
__device__ float d_ICt [K_ST * CDIM * CDIM];   // tf32(IC)
__device__ float d_IC  [K_ST * CDIM * CDIM];
__device__ float d_mp  [K_ST * CDIM];
__device__ float d_logdet[K_ST];
__device__ float d_lt  [K_ST * K_ST];
__device__ float d_linit[K_ST];
__device__ int   d_next[K_ST];
__device__ float d_elp [BATCH * LSEQ * K_ST];
__device__ int   d_states[BATCH * PRED];
__device__ float d_Wphi[K_ST * CDIM * FDIM];
__device__ float d_Wplo[K_ST * CDIM * FDIM];
__device__ float d_winhi[BATCH * 80 * CDIM];
__device__ float d_winlo[BATCH * 80 * CDIM];
__device__ int   d_perm[BATCH];
__device__ int   d_goff[K_ST];
__device__ int   d_gcnt[K_ST];
__device__ int   d_chain[K_ST * PRED];
__device__ float d_yem[BATCH * PRED * CDIM];

// ---------------------------------------------------------------------------
__device__ __forceinline__ float tf32r(float x) {
    uint32_t u;
    asm("cvt.rna.tf32.f32 %0, %1;" : "=r"(u) : "f"(x));
    return __uint_as_float(u);
}
__device__ __forceinline__ uint32_t smem_u32(const void* p) {
    uint32_t a;
    asm("{ .reg .u64 t; cvta.to.shared.u64 t, %1; cvt.u32.u64 %0, t; }"
        : "=r"(a) : "l"(p));
    return a;
}
__device__ __forceinline__ void cpa16(uint32_t dst, const void* src) {
    asm volatile("cp.async.cg.shared.global [%0], [%1], 16;" :: "r"(dst), "l"(src));
}
#define CP_COMMIT() asm volatile("cp.async.commit_group;" ::: "memory")
#define CP_WAIT1()  asm volatile("cp.async.wait_group 1;" ::: "memory")
#define CP_WAIT0()  asm volatile("cp.async.wait_group 0;" ::: "memory")

__device__ __forceinline__ void mma8(float c[4], const uint32_t a[4],
                                     uint32_t b0, uint32_t b1) {
    asm volatile(
        "mma.sync.aligned.m16n8k8.row.col.f32.tf32.tf32.f32 "
        "{%0,%1,%2,%3},{%4,%5,%6,%7},{%8,%9},{%0,%1,%2,%3};"
        : "+f"(c[0]), "+f"(c[1]), "+f"(c[2]), "+f"(c[3])
        : "r"(a[0]), "r"(a[1]), "r"(a[2]), "r"(a[3]), "r"(b0), "r"(b1));
}

// ---------------------------------------------------------------------------
__global__ void prep_small(const float* __restrict__ tm,
                           const float* __restrict__ initd)
{
    int tid = threadIdx.x;
    if (tid < K_ST) {
        float row[K_ST];
        float m = -1e30f;
        for (int j = 0; j < K_ST; ++j) { row[j] = tm[tid * K_ST + j]; m = fmaxf(m, row[j]); }
        float s = 0.f;
        for (int j = 0; j < K_ST; ++j) s += expf(row[j] - m);
        float lse = m + logf(s);
        for (int j = 0; j < K_ST; ++j)
            d_lt[tid * K_ST + j] = logf(expf(row[j] - lse) + 1e-8f);
        int arg = 0; float best = row[0];
        for (int j = 1; j < K_ST; ++j) if (row[j] > best) { best = row[j]; arg = j; }
        d_next[tid] = arg;
    }
    if (tid == 8) {
        float m = -1e30f;
        for (int j = 0; j < K_ST; ++j) m = fmaxf(m, initd[j]);
        float s = 0.f;
        for (int j = 0; j < K_ST; ++j) s += expf(initd[j] - m);
        float lse = m + logf(s);
        for (int j = 0; j < K_ST; ++j) d_linit[j] = initd[j] - lse;
    }
}

// ---------------------------------------------------------------------------
__global__ void prep_chol(const float* __restrict__ cchol,
                          const float* __restrict__ means)
{
    __shared__ float T[CDIM * CDIM];
    __shared__ float Cv[CDIM * CDIM];
    int tid = threadIdx.x;
    int k = blockIdx.x;

    for (int idx = tid; idx < CDIM * CDIM; idx += 256) {
        int i = idx >> 6, j = idx & 63;
        float v = cchol[k * CDIM * CDIM + idx];
        T[idx] = (j > i) ? 0.f : (j == i ? expf(v) : v);
    }
    __syncthreads();
    for (int idx = tid; idx < CDIM * CDIM; idx += 256) {
        int i = idx >> 6, j = idx & 63;
        int mmax = (i < j) ? i : j;
        float s = (i == j) ? 1e-6f : 0.f;
        for (int m = 0; m <= mmax; ++m) s += T[i * 64 + m] * T[j * 64 + m];
        Cv[idx] = s;
    }
    __syncthreads();
    for (int c = 0; c < CDIM; ++c) {
        if (tid == 0) Cv[c * 64 + c] = sqrtf(Cv[c * 64 + c]);
        __syncthreads();
        float dinv = 1.f / Cv[c * 64 + c];
        for (int i = c + 1 + tid; i < CDIM; i += 256) Cv[i * 64 + c] *= dinv;
        __syncthreads();
        for (int idx = tid; idx < CDIM * CDIM; idx += 256) {
            int i = idx >> 6, m = idx & 63;
            if (i > c && m > c && m <= i)
                Cv[i * 64 + m] -= Cv[i * 64 + c] * Cv[m * 64 + c];
        }
        __syncthreads();
    }
    if (tid == 0) {
        float s = 0.f;
        for (int i = 0; i < CDIM; ++i) s += logf(Cv[i * 64 + i]);
        d_logdet[k] = s;
    }
    for (int idx = tid; idx < CDIM * CDIM; idx += 256) T[idx] = 0.f;
    __syncthreads();
    if (tid < CDIM) {
        int c = tid;
        T[c * 64 + c] = 1.f / Cv[c * 64 + c];
        for (int i = c + 1; i < CDIM; ++i) {
            float s = 0.f;
            for (int m = c; m < i; ++m) s += Cv[i * 64 + m] * T[m * 64 + c];
            T[i * 64 + c] = -s / Cv[i * 64 + i];
        }
    }
    __syncthreads();
    for (int idx = tid; idx < CDIM * CDIM; idx += 256) {
        float v = T[idx];
        d_IC[k * CDIM * CDIM + idx] = v;
        d_ICt[k * CDIM * CDIM + idx] = tf32r(v);
    }
    if (tid < CDIM) {
        float s = 0.f;
        for (int j = 0; j < CDIM; ++j) s += T[tid * 64 + j] * means[k * CDIM + j];
        d_mp[k * CDIM + tid] = s;
    }
}

// ---------------------------------------------------------------------------
__global__ __launch_bounds__(256) void wp2_kernel(const float* __restrict__ W)
{
    __shared__ float Wt[64 * 65];
    __shared__ float ICs[64 * 65];
    int f0 = blockIdx.x * 64, k = blockIdx.y;
    int tid = threadIdx.x;

    for (int idx = tid; idx < 4096; idx += 256) {
        int c = idx >> 6, c2 = idx & 63;
        ICs[c * 65 + c2] = d_IC[k * 4096 + c * 64 + c2];
        Wt[c * 65 + c2] = W[(size_t)k * CDIM * FDIM + c * FDIM + f0 + c2];
    }
    __syncthreads();

    int fi = tid & 63, cq = tid >> 6;
    #pragma unroll 4
    for (int t = 0; t < 16; ++t) {
        int c = cq * 16 + t;
        float s = 0.f;
        #pragma unroll 16
        for (int c2 = 0; c2 < 64; ++c2)
            s += ICs[c * 65 + c2] * Wt[c2 * 65 + fi];
        d_Wn[((size_t)(k * 64 + c)) * FDIM + f0 + fi] = tf32r(-s);
    }
}

// ---------------------------------------------------------------------------
__global__ void wsplit_kernel(const float* __restrict__ W)
{
    int i = blockIdx.x * 1024 + threadIdx.x * 4;
    #pragma unroll
    for (int j = 0; j < 4; ++j) {
        float v = W[i + j];
        float h = tf32r(v);
        d_Wphi[i + j] = h;
        d_Wplo[i + j] = tf32r(v - h);
    }
}

__global__ void win_init_kernel(const float* __restrict__ em)
{
    int b = blockIdx.x;
    for (int i = threadIdx.x; i < FDIM; i += 256) {
        float v = em[(size_t)b * FDIM + i];
        float h = tf32r(v);
        d_winhi[(size_t)b * 5120 + i] = h;
        d_winlo[(size_t)b * 5120 + i] = tf32r(v - h);
    }
}

// ---------------------------------------------------------------------------
// elp GEMM: zero-skip + 3-stage pipeline, 1 barrier per chunk.
// A panel stores only Toeplitz rows 32..127 (rows <49 never read by MMA).
// ---------------------------------------------------------------------------
#define GA_FLOATS (2 * 96 * AST)        // 13056
#define GB_STAGE  (64 * AST)            // 4352
#define GSMEM_BYTES ((GA_FLOATS + 3 * GB_STAGE) * 4)   // 104448

extern __shared__ float smf[];

__device__ __forceinline__ void g_fill_B(int l, int stage, int k,
                                         uint32_t sb, int tid)
{
    uint32_t base = sb + (GA_FLOATS + stage * GB_STAGE) * 4;
    for (int idx = tid; idx < 1024; idx += 256) {
        int n = idx >> 4, q = idx & 15;
        const float* src = (l < 64)
            ? d_Wn + ((size_t)(k * 64 + n)) * FDIM + l * 64 + q * 4
            : d_ICt + (k * 64 + n) * 64 + q * 4;
        cpa16(base + n * (AST * 4) + q * 16, src);
    }
    CP_COMMIT();
}

__global__ __launch_bounds__(256, 2) void gemm_elp(const float* __restrict__ em)
{
    uint32_t sb = smem_u32(smf);
    int tid = threadIdx.x;
    int wid = tid >> 5, lane = tid & 31;
    int g = lane >> 2, q4 = lane & 3;
    int bx = blockIdx.x, k = blockIdx.y;
    int b0 = bx * 2;

    g_fill_B(0, 0, k, sb, tid);
    g_fill_B(1, 1, k, sb, tid);

    // A panel (rows 32..127 of the Toeplitz panel; smem row = panel row - 32)
    // smem rows 0..31: zeros (panel rows 32..63)
    for (int idx = tid; idx < 2 * 32 * 17; idx += 256) {
        int b = idx / (32 * 17); int rem = idx - b * 32 * 17;
        int r = rem / 17, q = rem - r * 17;
        float4 z = make_float4(0.f, 0.f, 0.f, 0.f);
        *(float4*)(smf + b * 96 * AST + r * AST + q * 4) = z;
    }
    // smem rows 32..95: emissions (panel rows 64..127), tf32-rounded
    for (int idx = tid; idx < 2048; idx += 256) {
        int b = idx >> 10; int t = (idx >> 4) & 63; int q = idx & 15;
        float4 v = *(const float4*)(em + (((size_t)(b0 + b)) * 64 + t) * 64 + q * 4);
        float4 o = make_float4(tf32r(v.x), tf32r(v.y), tf32r(v.z), tf32r(v.w));
        *(float4*)(smf + b * 96 * AST + (32 + t) * AST + q * 4) = o;
    }

    int warpM = wid >> 1, warpN = wid & 1;
    int bp = warpM >> 1;
    int tb = (warpM & 1) * 32;
    const float* Ab = smf + bp * 96 * AST;

    float C[2][4][4];
    #pragma unroll
    for (int mt = 0; mt < 2; ++mt)
        #pragma unroll
        for (int nt = 0; nt < 4; ++nt)
            #pragma unroll
            for (int i = 0; i < 4; ++i) C[mt][nt][i] = 0.f;

    CP_WAIT1();         // fill(0) done
    __syncthreads();    // A panel + fill(0) visible

    int s = 0;
    for (int l = 0; l <= 64; ++l) {
        bool more = (l + 2 <= 64);
        if (more) {
            int s2 = s + 2; if (s2 >= 3) s2 -= 3;
            g_fill_B(l + 2, s2, k, sb, tid);
        }

        bool act0 = (l + tb) >= 49;
        bool act1 = (l + tb) >= 33;
        if (act1) {
            const float* Bs = smf + GA_FLOATS + s * GB_STAGE;
            int fbase = tb + l + g - 32;     // shifted A row base
            #pragma unroll
            for (int st = 0; st < 8; ++st) {
                int c = q4 + st * 8;
                uint32_t A1[4];
                {
                    const float* ar = Ab + (fbase + 16) * AST;
                    A1[0] = __float_as_uint(ar[c]);
                    A1[1] = __float_as_uint(ar[8 * AST + c]);
                    A1[2] = __float_as_uint(ar[c + 4]);
                    A1[3] = __float_as_uint(ar[8 * AST + c + 4]);
                }
                uint32_t A0[4];
                if (act0) {
                    const float* ar = Ab + fbase * AST;
                    A0[0] = __float_as_uint(ar[c]);
                    A0[1] = __float_as_uint(ar[8 * AST + c]);
                    A0[2] = __float_as_uint(ar[c + 4]);
                    A0[3] = __float_as_uint(ar[8 * AST + c + 4]);
                }
                #pragma unroll
                for (int nt = 0; nt < 4; ++nt) {
                    int n = warpN * 32 + nt * 8 + g;
                    uint32_t bv0 = __float_as_uint(Bs[n * AST + c]);
                    uint32_t bv1 = __float_as_uint(Bs[n * AST + c + 4]);
                    if (act0) mma8(C[0][nt], A0, bv0, bv1);
                    mma8(C[1][nt], A1, bv0, bv1);
                }
            }
        }

        if (more) CP_WAIT1(); else CP_WAIT0();
        __syncthreads();
        if (++s == 3) s = 0;
    }

    // epilogue: quad = sum_cols (D - mp)^2 -> elp
    float* qsm = smf + GA_FLOATS;
    float ldk = d_logdet[k];
    const float* mpk = d_mp + k * CDIM;

    #pragma unroll
    for (int mt = 0; mt < 2; ++mt) {
        #pragma unroll
        for (int rh = 0; rh < 2; ++rh) {
            float sum = 0.f;
            #pragma unroll
            for (int nt = 0; nt < 4; ++nt) {
                int col = warpN * 32 + nt * 8 + q4 * 2;
                float v0 = C[mt][nt][rh * 2 + 0] - mpk[col];
                float v1 = C[mt][nt][rh * 2 + 1] - mpk[col + 1];
                sum += v0 * v0 + v1 * v1;
            }
            sum += __shfl_xor_sync(0xffffffffu, sum, 1);
            sum += __shfl_xor_sync(0xffffffffu, sum, 2);
            if (q4 == 0) {
                int m = warpM * 32 + mt * 16 + rh * 8 + g;
                qsm[m * 2 + warpN] = sum;
            }
        }
    }
    __syncthreads();
    if (tid < 128) {
        int m = tid;
        float quad = qsm[m * 2] + qsm[m * 2 + 1];
        int b = b0 + (m >= 64), t = m & 63;
        const float C_LOG2PI = 64.f * 1.8378770664093453f;
        d_elp[(((size_t)b) * 64 + t) * 8 + k] = -0.5f * (C_LOG2PI + quad) - ldk;
    }
}

// ---------------------------------------------------------------------------
__global__ void forward_kernel()
{
    __shared__ float lt_s[K_ST * K_ST];
    int tid = threadIdx.x;
    for (int i = tid; i < K_ST * K_ST; i += 32) lt_s[i] = d_lt[i];
    __syncthreads();
    int b = blockIdx.x * 32 + tid;
    if (b >= BATCH) return;

    const float* e = d_elp + (size_t)b * LSEQ * K_ST;
    float la[K_ST];
    for (int k = 0; k < K_ST; ++k) la[k] = d_linit[k] + e[k];
    for (int t = 1; t < LSEQ; ++t) {
        const float* et = e + t * K_ST;
        float nla[K_ST];
        #pragma unroll
        for (int k = 0; k < K_ST; ++k) {
            float m = -1e30f;
            #pragma unroll
            for (int j = 0; j < K_ST; ++j) m = fmaxf(m, la[j] + lt_s[j * K_ST + k]);
            float s = 0.f;
            #pragma unroll
            for (int j = 0; j < K_ST; ++j) s += __expf(la[j] + lt_s[j * K_ST + k] - m);
            nla[k] = m + __logf(s) + et[k];
        }
        #pragma unroll
        for (int k = 0; k < K_ST; ++k) la[k] = nla[k];
    }
    int arg = 0; float best = la[0];
    for (int k = 1; k < K_ST; ++k) if (la[k] > best) { best = la[k]; arg = k; }
    int s = d_next[arg];
    for (int p = 0; p < PRED; ++p) { d_states[b * PRED + p] = s; s = d_next[s]; }
}

// ---------------------------------------------------------------------------
__global__ void group_kernel()
{
    __shared__ int cnt[K_ST], off[K_ST + 1], cur[K_ST];
    int tid = threadIdx.x;
    if (tid < K_ST) { cnt[tid] = 0; cur[tid] = 0; }
    __syncthreads();
    int g = d_states[tid * PRED];
    atomicAdd(&cnt[g], 1);
    __syncthreads();
    if (tid == 0) {
        off[0] = 0;
        for (int i = 0; i < K_ST; ++i) off[i + 1] = off[i] + cnt[i];
    }
    __syncthreads();
    int pos = off[g] + atomicAdd(&cur[g], 1);
    d_perm[pos] = tid;
    if (tid < K_ST) {
        d_gcnt[tid] = cnt[tid];
        d_goff[tid] = off[tid];
        int s = tid;
        for (int p = 0; p < PRED; ++p) { d_chain[tid * PRED + p] = s; s = d_next[s]; }
    }
}

// ---------------------------------------------------------------------------
#define PA_FLOATS (2 * 2 * 32 * PST)    // 8704
#define PB_STAGE  (2 * 64 * PST)        // 8704
#define PSMEM_BYTES ((PA_FLOATS + 2 * PB_STAGE) * 4)

__device__ __forceinline__ void p_fill2(int aframe, int bchunk, int stage, int k,
                                        int goff, int cnt, int row0,
                                        uint32_t sb, int tid)
{
    for (int idx = tid; idx < 1024; idx += 256) {
        int part = idx >> 9, i = (idx >> 4) & 31, q = idx & 15;
        int r = row0 + i; if (r >= cnt) r = row0;
        int b = d_perm[goff + r];
        const float* base = part ? d_winlo : d_winhi;
        const float* src = base + ((size_t)b * 80 + aframe) * 64 + q * 4;
        cpa16(sb + (stage * (2 * 32 * PST) + part * (32 * PST) + i * PST) * 4 + q * 16, src);
    }
    for (int idx = tid; idx < 2048; idx += 256) {
        int part = idx >> 10, n = (idx >> 4) & 63, q = idx & 15;
        const float* base = part ? d_Wplo : d_Wphi;
        const float* src = base + ((size_t)(k * 64 + n)) * FDIM + bchunk * 64 + q * 4;
        cpa16(sb + (PA_FLOATS + stage * PB_STAGE + part * (64 * PST) + n * PST) * 4 + q * 16, src);
    }
    CP_COMMIT();
}

__device__ __forceinline__ void p_mma(float C[2][4], int s, int warpM, int warpN,
                                      int gg, int q4)
{
    const float* Ahi = smf + s * (2 * 32 * PST);
    const float* Alo = Ahi + 32 * PST;
    const float* Bhi = smf + PA_FLOATS + s * PB_STAGE;
    const float* Blo = Bhi + 64 * PST;
    int r0 = warpM * 16 + gg;

    #pragma unroll
    for (int st = 0; st < 8; ++st) {
        int c = q4 + st * 8;
        uint32_t ah[4], al[4];
        ah[0] = __float_as_uint(Ahi[r0 * PST + c]);
        ah[1] = __float_as_uint(Ahi[(r0 + 8) * PST + c]);
        ah[2] = __float_as_uint(Ahi[r0 * PST + c + 4]);
        ah[3] = __float_as_uint(Ahi[(r0 + 8) * PST + c + 4]);
        al[0] = __float_as_uint(Alo[r0 * PST + c]);
        al[1] = __float_as_uint(Alo[(r0 + 8) * PST + c]);
        al[2] = __float_as_uint(Alo[r0 * PST + c + 4]);
        al[3] = __float_as_uint(Alo[(r0 + 8) * PST + c + 4]);
        #pragma unroll
        for (int nt = 0; nt < 2; ++nt) {
            int n = warpN * 16 + nt * 8 + gg;
            uint32_t bh0 = __float_as_uint(Bhi[n * PST + c]);
            uint32_t bh1 = __float_as_uint(Bhi[n * PST + c + 4]);
            uint32_t bl0 = __float_as_uint(Blo[n * PST + c]);
            uint32_t bl1 = __float_as_uint(Blo[n * PST + c + 4]);
            mma8(C[nt], ah, bh0, bh1);
            mma8(C[nt], ah, bl0, bl1);
            mma8(C[nt], al, bh0, bh1);
        }
    }
}

__global__ __launch_bounds__(256, 2) void pred_em()
{
    int p = blockIdx.y;
    int g = blockIdx.x >> 4, tile = blockIdx.x & 15;
    int cnt = d_gcnt[g];
    int row0 = tile * 32;
    if (row0 >= cnt) return;
    int goff = d_goff[g];
    int k = d_chain[g * PRED + p];

    uint32_t sb = smem_u32(smf);
    int tid = threadIdx.x;
    int wid = tid >> 5, lane = tid & 31;
    int gg = lane >> 2, q4 = lane & 3;
    int warpM = wid >> 2, warpN = wid & 3;

    float C[2][4];
    #pragma unroll
    for (int nt = 0; nt < 2; ++nt)
        #pragma unroll
        for (int i = 0; i < 4; ++i) C[nt][i] = 0.f;

    int nchunks = 64 - p;
    p_fill2(p, 0, 0, k, goff, cnt, row0, sb, tid);
    CP_WAIT0();
    __syncthreads();
    for (int j = 0; j < nchunks; ++j) {
        int s = j & 1;
        bool more = (j + 1 < nchunks);
        if (more) p_fill2(p + j + 1, j + 1, s ^ 1, k, goff, cnt, row0, sb, tid);
        p_mma(C, s, warpM, warpN, gg, q4);
        if (more) { CP_WAIT0(); __syncthreads(); }
    }

    #pragma unroll
    for (int nt = 0; nt < 2; ++nt)
        #pragma unroll
        for (int rh = 0; rh < 2; ++rh) {
            int m = warpM * 16 + rh * 8 + gg;
            int r = row0 + m;
            if (r < cnt) {
                int b = d_perm[goff + r];
                #pragma unroll
                for (int cc = 0; cc < 2; ++cc) {
                    int col = warpN * 16 + nt * 8 + q4 * 2 + cc;
                    d_yem[((size_t)b * PRED + p) * CDIM + col] = C[nt][rh * 2 + cc];
                }
            }
        }
}

__global__ __launch_bounds__(256, 2) void pred_rec(const float* __restrict__ means,
                                                   float* __restrict__ out, int p)
{
    int g = blockIdx.x >> 4, tile = blockIdx.x & 15;
    int cnt = d_gcnt[g];
    int row0 = tile * 32;
    if (row0 >= cnt) return;
    int goff = d_goff[g];
    int k = d_chain[g * PRED + p];

    uint32_t sb = smem_u32(smf);
    int tid = threadIdx.x;
    int wid = tid >> 5, lane = tid & 31;
    int gg = lane >> 2, q4 = lane & 3;
    int warpM = wid >> 2, warpN = wid & 3;

    float C[2][4];
    #pragma unroll
    for (int nt = 0; nt < 2; ++nt)
        #pragma unroll
        for (int i = 0; i < 4; ++i) C[nt][i] = 0.f;

    if (p > 0) {
        p_fill2(64, 64 - p, 0, k, goff, cnt, row0, sb, tid);
        CP_WAIT0();
        __syncthreads();
        for (int q = 0; q < p; ++q) {
            int s = q & 1;
            bool more = (q + 1 < p);
            if (more) p_fill2(64 + q + 1, 64 - p + q + 1, s ^ 1, k, goff, cnt, row0, sb, tid);
            p_mma(C, s, warpM, warpN, gg, q4);
            if (more) { CP_WAIT0(); __syncthreads(); }
        }
    }

    #pragma unroll
    for (int nt = 0; nt < 2; ++nt)
        #pragma unroll
        for (int rh = 0; rh < 2; ++rh) {
            int m = warpM * 16 + rh * 8 + gg;
            int r = row0 + m;
            if (r < cnt) {
                int b = d_perm[goff + r];
                #pragma unroll
                for (int cc = 0; cc < 2; ++cc) {
                    int col = warpN * 16 + nt * 8 + q4 * 2 + cc;
                    float v = C[nt][rh * 2 + cc]
                            + d_yem[((size_t)b * PRED + p) * CDIM + col]
                            + means[k * CDIM + col];
                    out[((size_t)b * PRED + p) * CDIM + col] = v;
                    float h = tf32r(v);
                    d_winhi[((size_t)b * 80 + 64 + p) * 64 + col] = h;
                    d_winlo[((size_t)b * 80 + 64 + p) * 64 + col] = tf32r(v - h);
                }
            }
        }
}

// ---------------------------------------------------------------------------
extern "C" void kernel_launch(void* const* d_in, const int* in_sizes, int n_in,
                              void* d_out, int out_size)
{
    const float* em    = (const float*)d_in[0];
    const float* tm    = (const float*)d_in[1];
    const float* initd = (const float*)d_in[2];
    const float* means = (const float*)d_in[3];
    const float* cchol = (const float*)d_in[4];
    const float* W     = (const float*)d_in[5];
    float* out = (float*)d_out;

    cudaFuncSetAttribute(gemm_elp, cudaFuncAttributeMaxDynamicSharedMemorySize,
                         GSMEM_BYTES);
    cudaFuncSetAttribute(pred_em, cudaFuncAttributeMaxDynamicSharedMemorySize,
                         PSMEM_BYTES);
    cudaFuncSetAttribute(pred_rec, cudaFuncAttributeMaxDynamicSharedMemorySize,
                         PSMEM_BYTES);

    prep_small<<<1, 32>>>(tm, initd);                           // 1
    prep_chol<<<8, 256>>>(cchol, means);                        // 2
    wp2_kernel<<<dim3(64, 8), 256>>>(W);                        // 3
    gemm_elp<<<dim3(256, 8), 256, GSMEM_BYTES>>>(em);           // 4 <- ncu slot
    forward_kernel<<<16, 32>>>();                               // 5
    wsplit_kernel<<<2048, 256>>>(W);                            // 6
    win_init_kernel<<<512, 256>>>(em);                          // 7
    group_kernel<<<1, 512>>>();                                 // 8
    pred_em<<<dim3(128, 16), 256, PSMEM_BYTES>>>();             // 9
    for (int p = 0; p < PRED; ++p)
        pred_rec<<<128, 256, PSMEM_BYTES>>>(means, out, p);
}

// round 11
// speedup vs baseline: 1.0013x; 1.0013x over previous
#include <cuda_runtime.h>
#include <math.h>
#include <stdint.h>

// ---------------------------------------------------------------------------
// LinearAutoregressiveHMM — round 11:
//  * gemm_elp reverted verbatim to the r8 version (fastest measured: 746us).
//  * 16 serial pred_rec launches fused into ONE persistent kernel with a
//    device-wide barrier between steps (128 CTAs, all resident).
// ---------------------------------------------------------------------------

#define K_ST   8
#define LSEQ   64
#define CDIM   64
#define BATCH  512
#define PRED   16
#define FDIM   4096
#define AST    68
#define PST    68

// static scratch
__device__ float d_Wn  [K_ST * CDIM * FDIM];
__device__ float d_ICt [K_ST * CDIM * CDIM];
__device__ float d_IC  [K_ST * CDIM * CDIM];
__device__ float d_mp  [K_ST * CDIM];
__device__ float d_logdet[K_ST];
__device__ float d_lt  [K_ST * K_ST];
__device__ float d_linit[K_ST];
__device__ int   d_next[K_ST];
__device__ float d_elp [BATCH * LSEQ * K_ST];
__device__ int   d_states[BATCH * PRED];
__device__ float d_Wphi[K_ST * CDIM * FDIM];
__device__ float d_Wplo[K_ST * CDIM * FDIM];
__device__ float d_winhi[BATCH * 80 * CDIM];
__device__ float d_winlo[BATCH * 80 * CDIM];
__device__ int   d_perm[BATCH];
__device__ int   d_goff[K_ST];
__device__ int   d_gcnt[K_ST];
__device__ int   d_chain[K_ST * PRED];
__device__ float d_yem[BATCH * PRED * CDIM];
__device__ unsigned int d_psync;

// ---------------------------------------------------------------------------
__device__ __forceinline__ float tf32r(float x) {
    uint32_t u;
    asm("cvt.rna.tf32.f32 %0, %1;" : "=r"(u) : "f"(x));
    return __uint_as_float(u);
}
__device__ __forceinline__ uint32_t smem_u32(const void* p) {
    uint32_t a;
    asm("{ .reg .u64 t; cvta.to.shared.u64 t, %1; cvt.u32.u64 %0, t; }"
        : "=r"(a) : "l"(p));
    return a;
}
__device__ __forceinline__ void cpa16(uint32_t dst, const void* src) {
    asm volatile("cp.async.cg.shared.global [%0], [%1], 16;" :: "r"(dst), "l"(src));
}
#define CP_COMMIT() asm volatile("cp.async.commit_group;" ::: "memory")
#define CP_WAIT1()  asm volatile("cp.async.wait_group 1;" ::: "memory")
#define CP_WAIT0()  asm volatile("cp.async.wait_group 0;" ::: "memory")

__device__ __forceinline__ void mma8(float c[4], const uint32_t a[4],
                                     uint32_t b0, uint32_t b1) {
    asm volatile(
        "mma.sync.aligned.m16n8k8.row.col.f32.tf32.tf32.f32 "
        "{%0,%1,%2,%3},{%4,%5,%6,%7},{%8,%9},{%0,%1,%2,%3};"
        : "+f"(c[0]), "+f"(c[1]), "+f"(c[2]), "+f"(c[3])
        : "r"(a[0]), "r"(a[1]), "r"(a[2]), "r"(a[3]), "r"(b0), "r"(b1));
}

// ---------------------------------------------------------------------------
__global__ void prep_small(const float* __restrict__ tm,
                           const float* __restrict__ initd)
{
    int tid = threadIdx.x;
    if (tid < K_ST) {
        float row[K_ST];
        float m = -1e30f;
        for (int j = 0; j < K_ST; ++j) { row[j] = tm[tid * K_ST + j]; m = fmaxf(m, row[j]); }
        float s = 0.f;
        for (int j = 0; j < K_ST; ++j) s += expf(row[j] - m);
        float lse = m + logf(s);
        for (int j = 0; j < K_ST; ++j)
            d_lt[tid * K_ST + j] = logf(expf(row[j] - lse) + 1e-8f);
        int arg = 0; float best = row[0];
        for (int j = 1; j < K_ST; ++j) if (row[j] > best) { best = row[j]; arg = j; }
        d_next[tid] = arg;
    }
    if (tid == 8) {
        float m = -1e30f;
        for (int j = 0; j < K_ST; ++j) m = fmaxf(m, initd[j]);
        float s = 0.f;
        for (int j = 0; j < K_ST; ++j) s += expf(initd[j] - m);
        float lse = m + logf(s);
        for (int j = 0; j < K_ST; ++j) d_linit[j] = initd[j] - lse;
    }
}

// ---------------------------------------------------------------------------
__global__ void prep_chol(const float* __restrict__ cchol,
                          const float* __restrict__ means)
{
    __shared__ float T[CDIM * CDIM];
    __shared__ float Cv[CDIM * CDIM];
    int tid = threadIdx.x;
    int k = blockIdx.x;

    for (int idx = tid; idx < CDIM * CDIM; idx += 256) {
        int i = idx >> 6, j = idx & 63;
        float v = cchol[k * CDIM * CDIM + idx];
        T[idx] = (j > i) ? 0.f : (j == i ? expf(v) : v);
    }
    __syncthreads();
    for (int idx = tid; idx < CDIM * CDIM; idx += 256) {
        int i = idx >> 6, j = idx & 63;
        int mmax = (i < j) ? i : j;
        float s = (i == j) ? 1e-6f : 0.f;
        for (int m = 0; m <= mmax; ++m) s += T[i * 64 + m] * T[j * 64 + m];
        Cv[idx] = s;
    }
    __syncthreads();
    for (int c = 0; c < CDIM; ++c) {
        if (tid == 0) Cv[c * 64 + c] = sqrtf(Cv[c * 64 + c]);
        __syncthreads();
        float dinv = 1.f / Cv[c * 64 + c];
        for (int i = c + 1 + tid; i < CDIM; i += 256) Cv[i * 64 + c] *= dinv;
        __syncthreads();
        for (int idx = tid; idx < CDIM * CDIM; idx += 256) {
            int i = idx >> 6, m = idx & 63;
            if (i > c && m > c && m <= i)
                Cv[i * 64 + m] -= Cv[i * 64 + c] * Cv[m * 64 + c];
        }
        __syncthreads();
    }
    if (tid == 0) {
        float s = 0.f;
        for (int i = 0; i < CDIM; ++i) s += logf(Cv[i * 64 + i]);
        d_logdet[k] = s;
    }
    for (int idx = tid; idx < CDIM * CDIM; idx += 256) T[idx] = 0.f;
    __syncthreads();
    if (tid < CDIM) {
        int c = tid;
        T[c * 64 + c] = 1.f / Cv[c * 64 + c];
        for (int i = c + 1; i < CDIM; ++i) {
            float s = 0.f;
            for (int m = c; m < i; ++m) s += Cv[i * 64 + m] * T[m * 64 + c];
            T[i * 64 + c] = -s / Cv[i * 64 + i];
        }
    }
    __syncthreads();
    for (int idx = tid; idx < CDIM * CDIM; idx += 256) {
        float v = T[idx];
        d_IC[k * CDIM * CDIM + idx] = v;
        d_ICt[k * CDIM * CDIM + idx] = tf32r(v);
    }
    if (tid < CDIM) {
        float s = 0.f;
        for (int j = 0; j < CDIM; ++j) s += T[tid * 64 + j] * means[k * CDIM + j];
        d_mp[k * CDIM + tid] = s;
    }
}

// ---------------------------------------------------------------------------
__global__ __launch_bounds__(256) void wp2_kernel(const float* __restrict__ W)
{
    __shared__ float Wt[64 * 65];
    __shared__ float ICs[64 * 65];
    int f0 = blockIdx.x * 64, k = blockIdx.y;
    int tid = threadIdx.x;

    for (int idx = tid; idx < 4096; idx += 256) {
        int c = idx >> 6, c2 = idx & 63;
        ICs[c * 65 + c2] = d_IC[k * 4096 + c * 64 + c2];
        Wt[c * 65 + c2] = W[(size_t)k * CDIM * FDIM + c * FDIM + f0 + c2];
    }
    __syncthreads();

    int fi = tid & 63, cq = tid >> 6;
    #pragma unroll 4
    for (int t = 0; t < 16; ++t) {
        int c = cq * 16 + t;
        float s = 0.f;
        #pragma unroll 16
        for (int c2 = 0; c2 < 64; ++c2)
            s += ICs[c * 65 + c2] * Wt[c2 * 65 + fi];
        d_Wn[((size_t)(k * 64 + c)) * FDIM + f0 + fi] = tf32r(-s);
    }
}

// ---------------------------------------------------------------------------
__global__ void wsplit_kernel(const float* __restrict__ W)
{
    int i = blockIdx.x * 1024 + threadIdx.x * 4;
    #pragma unroll
    for (int j = 0; j < 4; ++j) {
        float v = W[i + j];
        float h = tf32r(v);
        d_Wphi[i + j] = h;
        d_Wplo[i + j] = tf32r(v - h);
    }
}

__global__ void win_init_kernel(const float* __restrict__ em)
{
    int b = blockIdx.x;
    for (int i = threadIdx.x; i < FDIM; i += 256) {
        float v = em[(size_t)b * FDIM + i];
        float h = tf32r(v);
        d_winhi[(size_t)b * 5120 + i] = h;
        d_winlo[(size_t)b * 5120 + i] = tf32r(v - h);
    }
}

// ---------------------------------------------------------------------------
// elp GEMM — exact r8 version (fastest measured).
// ---------------------------------------------------------------------------
#define GA_FLOATS (2 * 128 * AST)       // 17408
#define GB_STAGE  (64 * AST)            // 4352
#define GSMEM_BYTES ((GA_FLOATS + 2 * GB_STAGE) * 4)

extern __shared__ float smf[];

__device__ __forceinline__ void g_fill_B(int l, int stage, int k,
                                         uint32_t sb, int tid)
{
    uint32_t base = sb + (GA_FLOATS + stage * GB_STAGE) * 4;
    for (int idx = tid; idx < 1024; idx += 256) {
        int n = idx >> 4, q = idx & 15;
        const float* src = (l < 64)
            ? d_Wn + ((size_t)(k * 64 + n)) * FDIM + l * 64 + q * 4
            : d_ICt + (k * 64 + n) * 64 + q * 4;
        cpa16(base + n * (AST * 4) + q * 16, src);
    }
    CP_COMMIT();
}

__global__ __launch_bounds__(256, 2) void gemm_elp(const float* __restrict__ em)
{
    uint32_t sb = smem_u32(smf);
    int tid = threadIdx.x;
    int wid = tid >> 5, lane = tid & 31;
    int g = lane >> 2, q4 = lane & 3;
    int bx = blockIdx.x, k = blockIdx.y;
    int b0 = bx * 2;

    g_fill_B(0, 0, k, sb, tid);

    // A panel: rows 0..63 zero, rows 64..127 = emissions (tf32)
    for (int idx = tid; idx < 2 * 64 * 17; idx += 256) {
        int b = idx / (64 * 17); int r = (idx / 17) & 63; int q = idx % 17;
        float4 z = make_float4(0.f, 0.f, 0.f, 0.f);
        *(float4*)(smf + b * 128 * AST + r * AST + q * 4) = z;
    }
    for (int idx = tid; idx < 2 * 64 * 16; idx += 256) {
        int b = idx >> 10; int t = (idx >> 4) & 63; int q = idx & 15;
        float4 v = *(const float4*)(em + (((size_t)(b0 + b)) * 64 + t) * 64 + q * 4);
        float4 o = make_float4(tf32r(v.x), tf32r(v.y), tf32r(v.z), tf32r(v.w));
        *(float4*)(smf + b * 128 * AST + (64 + t) * AST + q * 4) = o;
    }

    int warpM = wid >> 1, warpN = wid & 1;
    int bp = warpM >> 1;
    int tb = (warpM & 1) * 32;
    const float* Ab = smf + bp * 128 * AST;

    float C[2][4][4];
    #pragma unroll
    for (int mt = 0; mt < 2; ++mt)
        #pragma unroll
        for (int nt = 0; nt < 4; ++nt)
            #pragma unroll
            for (int i = 0; i < 4; ++i) C[mt][nt][i] = 0.f;

    for (int l = 0; l <= 64; ++l) {
        int s = l & 1;
        if (l < 64) { g_fill_B(l + 1, s ^ 1, k, sb, tid); CP_WAIT1(); }
        else        { CP_WAIT0(); }
        __syncthreads();

        bool act0 = (l + tb) >= 49;
        bool act1 = (l + tb) >= 33;
        if (act1) {
            const float* Bs = smf + GA_FLOATS + s * GB_STAGE;
            int fbase = tb + l + g;
            #pragma unroll
            for (int st = 0; st < 8; ++st) {
                int c = q4 + st * 8;
                uint32_t A1[4];
                {
                    const float* ar = Ab + (fbase + 16) * AST;
                    A1[0] = __float_as_uint(ar[c]);
                    A1[1] = __float_as_uint(ar[8 * AST + c]);
                    A1[2] = __float_as_uint(ar[c + 4]);
                    A1[3] = __float_as_uint(ar[8 * AST + c + 4]);
                }
                uint32_t A0[4];
                if (act0) {
                    const float* ar = Ab + fbase * AST;
                    A0[0] = __float_as_uint(ar[c]);
                    A0[1] = __float_as_uint(ar[8 * AST + c]);
                    A0[2] = __float_as_uint(ar[c + 4]);
                    A0[3] = __float_as_uint(ar[8 * AST + c + 4]);
                }
                #pragma unroll
                for (int nt = 0; nt < 4; ++nt) {
                    int n = warpN * 32 + nt * 8 + g;
                    uint32_t bv0 = __float_as_uint(Bs[n * AST + c]);
                    uint32_t bv1 = __float_as_uint(Bs[n * AST + c + 4]);
                    if (act0) mma8(C[0][nt], A0, bv0, bv1);
                    mma8(C[1][nt], A1, bv0, bv1);
                }
            }
        }
        __syncthreads();
    }

    // epilogue: quad = sum_cols (D - mp)^2 -> elp
    float* qsm = smf + GA_FLOATS;
    float ldk = d_logdet[k];
    const float* mpk = d_mp + k * CDIM;

    #pragma unroll
    for (int mt = 0; mt < 2; ++mt) {
        #pragma unroll
        for (int rh = 0; rh < 2; ++rh) {
            float sum = 0.f;
            #pragma unroll
            for (int nt = 0; nt < 4; ++nt) {
                int col = warpN * 32 + nt * 8 + q4 * 2;
                float v0 = C[mt][nt][rh * 2 + 0] - mpk[col];
                float v1 = C[mt][nt][rh * 2 + 1] - mpk[col + 1];
                sum += v0 * v0 + v1 * v1;
            }
            sum += __shfl_xor_sync(0xffffffffu, sum, 1);
            sum += __shfl_xor_sync(0xffffffffu, sum, 2);
            if (q4 == 0) {
                int m = warpM * 32 + mt * 16 + rh * 8 + g;
                qsm[m * 2 + warpN] = sum;
            }
        }
    }
    __syncthreads();
    if (tid < 128) {
        int m = tid;
        float quad = qsm[m * 2] + qsm[m * 2 + 1];
        int b = b0 + (m >= 64), t = m & 63;
        const float C_LOG2PI = 64.f * 1.8378770664093453f;
        d_elp[(((size_t)b) * 64 + t) * 8 + k] = -0.5f * (C_LOG2PI + quad) - ldk;
    }
}

// ---------------------------------------------------------------------------
__global__ void forward_kernel()
{
    __shared__ float lt_s[K_ST * K_ST];
    int tid = threadIdx.x;
    for (int i = tid; i < K_ST * K_ST; i += 32) lt_s[i] = d_lt[i];
    __syncthreads();
    int b = blockIdx.x * 32 + tid;
    if (b >= BATCH) return;

    const float* e = d_elp + (size_t)b * LSEQ * K_ST;
    float la[K_ST];
    for (int k = 0; k < K_ST; ++k) la[k] = d_linit[k] + e[k];
    for (int t = 1; t < LSEQ; ++t) {
        const float* et = e + t * K_ST;
        float nla[K_ST];
        #pragma unroll
        for (int k = 0; k < K_ST; ++k) {
            float m = -1e30f;
            #pragma unroll
            for (int j = 0; j < K_ST; ++j) m = fmaxf(m, la[j] + lt_s[j * K_ST + k]);
            float s = 0.f;
            #pragma unroll
            for (int j = 0; j < K_ST; ++j) s += __expf(la[j] + lt_s[j * K_ST + k] - m);
            nla[k] = m + __logf(s) + et[k];
        }
        #pragma unroll
        for (int k = 0; k < K_ST; ++k) la[k] = nla[k];
    }
    int arg = 0; float best = la[0];
    for (int k = 1; k < K_ST; ++k) if (la[k] > best) { best = la[k]; arg = k; }
    int s = d_next[arg];
    for (int p = 0; p < PRED; ++p) { d_states[b * PRED + p] = s; s = d_next[s]; }
}

// ---------------------------------------------------------------------------
__global__ void group_kernel()
{
    __shared__ int cnt[K_ST], off[K_ST + 1], cur[K_ST];
    int tid = threadIdx.x;
    if (tid == 0) d_psync = 0u;          // reset persistent-kernel barrier
    if (tid < K_ST) { cnt[tid] = 0; cur[tid] = 0; }
    __syncthreads();
    int g = d_states[tid * PRED];
    atomicAdd(&cnt[g], 1);
    __syncthreads();
    if (tid == 0) {
        off[0] = 0;
        for (int i = 0; i < K_ST; ++i) off[i + 1] = off[i] + cnt[i];
    }
    __syncthreads();
    int pos = off[g] + atomicAdd(&cur[g], 1);
    d_perm[pos] = tid;
    if (tid < K_ST) {
        d_gcnt[tid] = cnt[tid];
        d_goff[tid] = off[tid];
        int s = tid;
        for (int p = 0; p < PRED; ++p) { d_chain[tid * PRED + p] = s; s = d_next[s]; }
    }
}

// ---------------------------------------------------------------------------
#define PA_FLOATS (2 * 2 * 32 * PST)    // 8704
#define PB_STAGE  (2 * 64 * PST)        // 8704
#define PSMEM_BYTES ((PA_FLOATS + 2 * PB_STAGE) * 4)

__device__ __forceinline__ void p_fill2(int aframe, int bchunk, int stage, int k,
                                        int goff, int cnt, int row0,
                                        uint32_t sb, int tid)
{
    for (int idx = tid; idx < 1024; idx += 256) {
        int part = idx >> 9, i = (idx >> 4) & 31, q = idx & 15;
        int r = row0 + i; if (r >= cnt) r = row0;
        int b = d_perm[goff + r];
        const float* base = part ? d_winlo : d_winhi;
        const float* src = base + ((size_t)b * 80 + aframe) * 64 + q * 4;
        cpa16(sb + (stage * (2 * 32 * PST) + part * (32 * PST) + i * PST) * 4 + q * 16, src);
    }
    for (int idx = tid; idx < 2048; idx += 256) {
        int part = idx >> 10, n = (idx >> 4) & 63, q = idx & 15;
        const float* base = part ? d_Wplo : d_Wphi;
        const float* src = base + ((size_t)(k * 64 + n)) * FDIM + bchunk * 64 + q * 4;
        cpa16(sb + (PA_FLOATS + stage * PB_STAGE + part * (64 * PST) + n * PST) * 4 + q * 16, src);
    }
    CP_COMMIT();
}

__device__ __forceinline__ void p_mma(float C[2][4], int s, int warpM, int warpN,
                                      int gg, int q4)
{
    const float* Ahi = smf + s * (2 * 32 * PST);
    const float* Alo = Ahi + 32 * PST;
    const float* Bhi = smf + PA_FLOATS + s * PB_STAGE;
    const float* Blo = Bhi + 64 * PST;
    int r0 = warpM * 16 + gg;

    #pragma unroll
    for (int st = 0; st < 8; ++st) {
        int c = q4 + st * 8;
        uint32_t ah[4], al[4];
        ah[0] = __float_as_uint(Ahi[r0 * PST + c]);
        ah[1] = __float_as_uint(Ahi[(r0 + 8) * PST + c]);
        ah[2] = __float_as_uint(Ahi[r0 * PST + c + 4]);
        ah[3] = __float_as_uint(Ahi[(r0 + 8) * PST + c + 4]);
        al[0] = __float_as_uint(Alo[r0 * PST + c]);
        al[1] = __float_as_uint(Alo[(r0 + 8) * PST + c]);
        al[2] = __float_as_uint(Alo[r0 * PST + c + 4]);
        al[3] = __float_as_uint(Alo[(r0 + 8) * PST + c + 4]);
        #pragma unroll
        for (int nt = 0; nt < 2; ++nt) {
            int n = warpN * 16 + nt * 8 + gg;
            uint32_t bh0 = __float_as_uint(Bhi[n * PST + c]);
            uint32_t bh1 = __float_as_uint(Bhi[n * PST + c + 4]);
            uint32_t bl0 = __float_as_uint(Blo[n * PST + c]);
            uint32_t bl1 = __float_as_uint(Blo[n * PST + c + 4]);
            mma8(C[nt], ah, bh0, bh1);
            mma8(C[nt], ah, bl0, bl1);
            mma8(C[nt], al, bh0, bh1);
        }
    }
}

__global__ __launch_bounds__(256, 2) void pred_em()
{
    int p = blockIdx.y;
    int g = blockIdx.x >> 4, tile = blockIdx.x & 15;
    int cnt = d_gcnt[g];
    int row0 = tile * 32;
    if (row0 >= cnt) return;
    int goff = d_goff[g];
    int k = d_chain[g * PRED + p];

    uint32_t sb = smem_u32(smf);
    int tid = threadIdx.x;
    int wid = tid >> 5, lane = tid & 31;
    int gg = lane >> 2, q4 = lane & 3;
    int warpM = wid >> 2, warpN = wid & 3;

    float C[2][4];
    #pragma unroll
    for (int nt = 0; nt < 2; ++nt)
        #pragma unroll
        for (int i = 0; i < 4; ++i) C[nt][i] = 0.f;

    int nchunks = 64 - p;
    p_fill2(p, 0, 0, k, goff, cnt, row0, sb, tid);
    for (int j = 0; j < nchunks; ++j) {
        int s = j & 1;
        if (j < nchunks - 1) {
            p_fill2(p + j + 1, j + 1, s ^ 1, k, goff, cnt, row0, sb, tid);
            CP_WAIT1();
        } else CP_WAIT0();
        __syncthreads();
        p_mma(C, s, warpM, warpN, gg, q4);
        __syncthreads();
    }

    #pragma unroll
    for (int nt = 0; nt < 2; ++nt)
        #pragma unroll
        for (int rh = 0; rh < 2; ++rh) {
            int m = warpM * 16 + rh * 8 + gg;
            int r = row0 + m;
            if (r < cnt) {
                int b = d_perm[goff + r];
                #pragma unroll
                for (int cc = 0; cc < 2; ++cc) {
                    int col = warpN * 16 + nt * 8 + q4 * 2 + cc;
                    d_yem[((size_t)b * PRED + p) * CDIM + col] = C[nt][rh * 2 + cc];
                }
            }
        }
}

// ---------------------------------------------------------------------------
// persistent recurrent pred: all 16 steps in one kernel, device-wide barrier.
// 128 CTAs (g, tile); ALL CTAs join every barrier (no early return).
// ---------------------------------------------------------------------------
__global__ __launch_bounds__(256, 2) void pred_rec_persist(
    const float* __restrict__ means, float* __restrict__ out)
{
    int bid = blockIdx.x;
    int g = bid >> 4, tile = bid & 15;
    int goff = d_goff[g];
    int cnt = d_gcnt[g];
    int row0 = tile * 32;
    bool active = (row0 < cnt);

    uint32_t sb = smem_u32(smf);
    int tid = threadIdx.x;
    int wid = tid >> 5, lane = tid & 31;
    int gg = lane >> 2, q4 = lane & 3;
    int warpM = wid >> 2, warpN = wid & 3;

    for (int p = 0; p < PRED; ++p) {
        int k = d_chain[g * PRED + p];

        float C[2][4];
        #pragma unroll
        for (int nt = 0; nt < 2; ++nt)
            #pragma unroll
            for (int i = 0; i < 4; ++i) C[nt][i] = 0.f;

        if (active && p > 0) {
            p_fill2(64, 64 - p, 0, k, goff, cnt, row0, sb, tid);
            for (int q = 0; q < p; ++q) {
                int s = q & 1;
                if (q < p - 1) {
                    p_fill2(64 + q + 1, 64 - p + q + 1, s ^ 1, k, goff, cnt, row0, sb, tid);
                    CP_WAIT1();
                } else CP_WAIT0();
                __syncthreads();
                p_mma(C, s, warpM, warpN, gg, q4);
                __syncthreads();
            }
        }

        if (active) {
            #pragma unroll
            for (int nt = 0; nt < 2; ++nt)
                #pragma unroll
                for (int rh = 0; rh < 2; ++rh) {
                    int m = warpM * 16 + rh * 8 + gg;
                    int r = row0 + m;
                    if (r < cnt) {
                        int b = d_perm[goff + r];
                        #pragma unroll
                        for (int cc = 0; cc < 2; ++cc) {
                            int col = warpN * 16 + nt * 8 + q4 * 2 + cc;
                            float v = C[nt][rh * 2 + cc]
                                    + d_yem[((size_t)b * PRED + p) * CDIM + col]
                                    + means[k * CDIM + col];
                            out[((size_t)b * PRED + p) * CDIM + col] = v;
                            float h = tf32r(v);
                            d_winhi[((size_t)b * 80 + 64 + p) * 64 + col] = h;
                            d_winlo[((size_t)b * 80 + 64 + p) * 64 + col] = tf32r(v - h);
                        }
                    }
                }
        }

        // device-wide barrier between steps (skip after the last step)
        if (p < PRED - 1) {
            __threadfence();
            __syncthreads();
            if (tid == 0) {
                atomicAdd(&d_psync, 1u);
                unsigned target = (unsigned)gridDim.x * (unsigned)(p + 1);
                unsigned v;
                do {
                    asm volatile("ld.acquire.gpu.u32 %0, [%1];"
                                 : "=r"(v) : "l"(&d_psync));
                    if (v < target) __nanosleep(64);
                } while (v < target);
            }
            __syncthreads();
            __threadfence();
        }
    }
}

// ---------------------------------------------------------------------------
extern "C" void kernel_launch(void* const* d_in, const int* in_sizes, int n_in,
                              void* d_out, int out_size)
{
    const float* em    = (const float*)d_in[0];
    const float* tm    = (const float*)d_in[1];
    const float* initd = (const float*)d_in[2];
    const float* means = (const float*)d_in[3];
    const float* cchol = (const float*)d_in[4];
    const float* W     = (const float*)d_in[5];
    float* out = (float*)d_out;

    cudaFuncSetAttribute(gemm_elp, cudaFuncAttributeMaxDynamicSharedMemorySize,
                         GSMEM_BYTES);
    cudaFuncSetAttribute(pred_em, cudaFuncAttributeMaxDynamicSharedMemorySize,
                         PSMEM_BYTES);
    cudaFuncSetAttribute(pred_rec_persist, cudaFuncAttributeMaxDynamicSharedMemorySize,
                         PSMEM_BYTES);

    prep_small<<<1, 32>>>(tm, initd);                           // 1
    prep_chol<<<8, 256>>>(cchol, means);                        // 2
    wp2_kernel<<<dim3(64, 8), 256>>>(W);                        // 3
    gemm_elp<<<dim3(256, 8), 256, GSMEM_BYTES>>>(em);           // 4 <- ncu slot
    forward_kernel<<<16, 32>>>();                               // 5
    wsplit_kernel<<<2048, 256>>>(W);                            // 6
    win_init_kernel<<<512, 256>>>(em);                          // 7
    group_kernel<<<1, 512>>>();                                 // 8
    pred_em<<<dim3(128, 16), 256, PSMEM_BYTES>>>();             // 9
    pred_rec_persist<<<128, 256, PSMEM_BYTES>>>(means, out);    // 10
}

// round 12
// speedup vs baseline: 1.0131x; 1.0118x over previous
#include <cuda_runtime.h>
#include <math.h>
#include <stdint.h>

// ---------------------------------------------------------------------------
// LinearAutoregressiveHMM — round 12:
//  * gemm_elp occupancy fix: M=64 (1 batch) per CTA with k-split warp layout
//    (2x2x2 warps); smem 69.6KB/CTA -> 3 CTAs/SM = 24 warps (was 16).
//    Same total LDS/MMA instruction counts as r8; pure latency-hiding win.
//  * everything else verbatim from r11 (persistent pred, zero-skip, etc).
// ---------------------------------------------------------------------------

#define K_ST   8
#define LSEQ   64
#define CDIM   64
#define BATCH  512
#define PRED   16
#define FDIM   4096
#define AST    68
#define PST    68

// static scratch
__device__ float d_Wn  [K_ST * CDIM * FDIM];
__device__ float d_ICt [K_ST * CDIM * CDIM];
__device__ float d_IC  [K_ST * CDIM * CDIM];
__device__ float d_mp  [K_ST * CDIM];
__device__ float d_logdet[K_ST];
__device__ float d_lt  [K_ST * K_ST];
__device__ float d_linit[K_ST];
__device__ int   d_next[K_ST];
__device__ float d_elp [BATCH * LSEQ * K_ST];
__device__ int   d_states[BATCH * PRED];
__device__ float d_Wphi[K_ST * CDIM * FDIM];
__device__ float d_Wplo[K_ST * CDIM * FDIM];
__device__ float d_winhi[BATCH * 80 * CDIM];
__device__ float d_winlo[BATCH * 80 * CDIM];
__device__ int   d_perm[BATCH];
__device__ int   d_goff[K_ST];
__device__ int   d_gcnt[K_ST];
__device__ int   d_chain[K_ST * PRED];
__device__ float d_yem[BATCH * PRED * CDIM];
__device__ unsigned int d_psync;

// ---------------------------------------------------------------------------
__device__ __forceinline__ float tf32r(float x) {
    uint32_t u;
    asm("cvt.rna.tf32.f32 %0, %1;" : "=r"(u) : "f"(x));
    return __uint_as_float(u);
}
__device__ __forceinline__ uint32_t smem_u32(const void* p) {
    uint32_t a;
    asm("{ .reg .u64 t; cvta.to.shared.u64 t, %1; cvt.u32.u64 %0, t; }"
        : "=r"(a) : "l"(p));
    return a;
}
__device__ __forceinline__ void cpa16(uint32_t dst, const void* src) {
    asm volatile("cp.async.cg.shared.global [%0], [%1], 16;" :: "r"(dst), "l"(src));
}
#define CP_COMMIT() asm volatile("cp.async.commit_group;" ::: "memory")
#define CP_WAIT1()  asm volatile("cp.async.wait_group 1;" ::: "memory")
#define CP_WAIT0()  asm volatile("cp.async.wait_group 0;" ::: "memory")

__device__ __forceinline__ void mma8(float c[4], const uint32_t a[4],
                                     uint32_t b0, uint32_t b1) {
    asm volatile(
        "mma.sync.aligned.m16n8k8.row.col.f32.tf32.tf32.f32 "
        "{%0,%1,%2,%3},{%4,%5,%6,%7},{%8,%9},{%0,%1,%2,%3};"
        : "+f"(c[0]), "+f"(c[1]), "+f"(c[2]), "+f"(c[3])
        : "r"(a[0]), "r"(a[1]), "r"(a[2]), "r"(a[3]), "r"(b0), "r"(b1));
}

// ---------------------------------------------------------------------------
__global__ void prep_small(const float* __restrict__ tm,
                           const float* __restrict__ initd)
{
    int tid = threadIdx.x;
    if (tid < K_ST) {
        float row[K_ST];
        float m = -1e30f;
        for (int j = 0; j < K_ST; ++j) { row[j] = tm[tid * K_ST + j]; m = fmaxf(m, row[j]); }
        float s = 0.f;
        for (int j = 0; j < K_ST; ++j) s += expf(row[j] - m);
        float lse = m + logf(s);
        for (int j = 0; j < K_ST; ++j)
            d_lt[tid * K_ST + j] = logf(expf(row[j] - lse) + 1e-8f);
        int arg = 0; float best = row[0];
        for (int j = 1; j < K_ST; ++j) if (row[j] > best) { best = row[j]; arg = j; }
        d_next[tid] = arg;
    }
    if (tid == 8) {
        float m = -1e30f;
        for (int j = 0; j < K_ST; ++j) m = fmaxf(m, initd[j]);
        float s = 0.f;
        for (int j = 0; j < K_ST; ++j) s += expf(initd[j] - m);
        float lse = m + logf(s);
        for (int j = 0; j < K_ST; ++j) d_linit[j] = initd[j] - lse;
    }
}

// ---------------------------------------------------------------------------
__global__ void prep_chol(const float* __restrict__ cchol,
                          const float* __restrict__ means)
{
    __shared__ float T[CDIM * CDIM];
    __shared__ float Cv[CDIM * CDIM];
    int tid = threadIdx.x;
    int k = blockIdx.x;

    for (int idx = tid; idx < CDIM * CDIM; idx += 256) {
        int i = idx >> 6, j = idx & 63;
        float v = cchol[k * CDIM * CDIM + idx];
        T[idx] = (j > i) ? 0.f : (j == i ? expf(v) : v);
    }
    __syncthreads();
    for (int idx = tid; idx < CDIM * CDIM; idx += 256) {
        int i = idx >> 6, j = idx & 63;
        int mmax = (i < j) ? i : j;
        float s = (i == j) ? 1e-6f : 0.f;
        for (int m = 0; m <= mmax; ++m) s += T[i * 64 + m] * T[j * 64 + m];
        Cv[idx] = s;
    }
    __syncthreads();
    for (int c = 0; c < CDIM; ++c) {
        if (tid == 0) Cv[c * 64 + c] = sqrtf(Cv[c * 64 + c]);
        __syncthreads();
        float dinv = 1.f / Cv[c * 64 + c];
        for (int i = c + 1 + tid; i < CDIM; i += 256) Cv[i * 64 + c] *= dinv;
        __syncthreads();
        for (int idx = tid; idx < CDIM * CDIM; idx += 256) {
            int i = idx >> 6, m = idx & 63;
            if (i > c && m > c && m <= i)
                Cv[i * 64 + m] -= Cv[i * 64 + c] * Cv[m * 64 + c];
        }
        __syncthreads();
    }
    if (tid == 0) {
        float s = 0.f;
        for (int i = 0; i < CDIM; ++i) s += logf(Cv[i * 64 + i]);
        d_logdet[k] = s;
    }
    for (int idx = tid; idx < CDIM * CDIM; idx += 256) T[idx] = 0.f;
    __syncthreads();
    if (tid < CDIM) {
        int c = tid;
        T[c * 64 + c] = 1.f / Cv[c * 64 + c];
        for (int i = c + 1; i < CDIM; ++i) {
            float s = 0.f;
            for (int m = c; m < i; ++m) s += Cv[i * 64 + m] * T[m * 64 + c];
            T[i * 64 + c] = -s / Cv[i * 64 + i];
        }
    }
    __syncthreads();
    for (int idx = tid; idx < CDIM * CDIM; idx += 256) {
        float v = T[idx];
        d_IC[k * CDIM * CDIM + idx] = v;
        d_ICt[k * CDIM * CDIM + idx] = tf32r(v);
    }
    if (tid < CDIM) {
        float s = 0.f;
        for (int j = 0; j < CDIM; ++j) s += T[tid * 64 + j] * means[k * CDIM + j];
        d_mp[k * CDIM + tid] = s;
    }
}

// ---------------------------------------------------------------------------
__global__ __launch_bounds__(256) void wp2_kernel(const float* __restrict__ W)
{
    __shared__ float Wt[64 * 65];
    __shared__ float ICs[64 * 65];
    int f0 = blockIdx.x * 64, k = blockIdx.y;
    int tid = threadIdx.x;

    for (int idx = tid; idx < 4096; idx += 256) {
        int c = idx >> 6, c2 = idx & 63;
        ICs[c * 65 + c2] = d_IC[k * 4096 + c * 64 + c2];
        Wt[c * 65 + c2] = W[(size_t)k * CDIM * FDIM + c * FDIM + f0 + c2];
    }
    __syncthreads();

    int fi = tid & 63, cq = tid >> 6;
    #pragma unroll 4
    for (int t = 0; t < 16; ++t) {
        int c = cq * 16 + t;
        float s = 0.f;
        #pragma unroll 16
        for (int c2 = 0; c2 < 64; ++c2)
            s += ICs[c * 65 + c2] * Wt[c2 * 65 + fi];
        d_Wn[((size_t)(k * 64 + c)) * FDIM + f0 + fi] = tf32r(-s);
    }
}

// ---------------------------------------------------------------------------
__global__ void wsplit_kernel(const float* __restrict__ W)
{
    int i = blockIdx.x * 1024 + threadIdx.x * 4;
    #pragma unroll
    for (int j = 0; j < 4; ++j) {
        float v = W[i + j];
        float h = tf32r(v);
        d_Wphi[i + j] = h;
        d_Wplo[i + j] = tf32r(v - h);
    }
}

__global__ void win_init_kernel(const float* __restrict__ em)
{
    int b = blockIdx.x;
    for (int i = threadIdx.x; i < FDIM; i += 256) {
        float v = em[(size_t)b * FDIM + i];
        float h = tf32r(v);
        d_winhi[(size_t)b * 5120 + i] = h;
        d_winlo[(size_t)b * 5120 + i] = tf32r(v - h);
    }
}

// ---------------------------------------------------------------------------
// elp GEMM: M=64 (1 batch) per CTA, warp layout (warpM 2) x (warpN 2) x (ks 2).
// Each warp: 4 of 8 k-slices per chunk; C reduced across ks at the epilogue.
// smem 69.6KB -> 3 CTAs/SM (24 warps).
// ---------------------------------------------------------------------------
#define GA_FLOATS (128 * AST)           // 8704
#define GB_STAGE  (64 * AST)            // 4352
#define GSMEM_BYTES ((GA_FLOATS + 2 * GB_STAGE) * 4)   // 69632

extern __shared__ float smf[];

__device__ __forceinline__ void g_fill_B(int l, int stage, int k,
                                         uint32_t sb, int tid)
{
    uint32_t base = sb + (GA_FLOATS + stage * GB_STAGE) * 4;
    for (int idx = tid; idx < 1024; idx += 256) {
        int n = idx >> 4, q = idx & 15;
        const float* src = (l < 64)
            ? d_Wn + ((size_t)(k * 64 + n)) * FDIM + l * 64 + q * 4
            : d_ICt + (k * 64 + n) * 64 + q * 4;
        cpa16(base + n * (AST * 4) + q * 16, src);
    }
    CP_COMMIT();
}

__global__ __launch_bounds__(256, 3) void gemm_elp(const float* __restrict__ em)
{
    uint32_t sb = smem_u32(smf);
    int tid = threadIdx.x;
    int wid = tid >> 5, lane = tid & 31;
    int g = lane >> 2, q4 = lane & 3;
    int b = blockIdx.x, k = blockIdx.y;

    g_fill_B(0, 0, k, sb, tid);

    // A panel: rows 0..63 zero, rows 64..127 = emissions[b] (tf32)
    for (int idx = tid; idx < 64 * 17; idx += 256) {
        int r = idx / 17, q = idx % 17;
        float4 z = make_float4(0.f, 0.f, 0.f, 0.f);
        *(float4*)(smf + r * AST + q * 4) = z;
    }
    for (int idx = tid; idx < 64 * 16; idx += 256) {
        int t = idx >> 4, q = idx & 15;
        float4 v = *(const float4*)(em + (((size_t)b) * 64 + t) * 64 + q * 4);
        float4 o = make_float4(tf32r(v.x), tf32r(v.y), tf32r(v.z), tf32r(v.w));
        *(float4*)(smf + (64 + t) * AST + q * 4) = o;
    }

    int warpM = wid >> 2;          // 0..1 : M 32-row tile pair
    int warpN = (wid >> 1) & 1;    // 0..1 : N 32-col half
    int ks    = wid & 1;           // 0..1 : k-slice half (st 0-3 / 4-7)
    int tb = warpM * 32;
    const float* Ab = smf;

    float C[2][4][4];
    #pragma unroll
    for (int mt = 0; mt < 2; ++mt)
        #pragma unroll
        for (int nt = 0; nt < 4; ++nt)
            #pragma unroll
            for (int i = 0; i < 4; ++i) C[mt][nt][i] = 0.f;

    for (int l = 0; l <= 64; ++l) {
        int s = l & 1;
        if (l < 64) { g_fill_B(l + 1, s ^ 1, k, sb, tid); CP_WAIT1(); }
        else        { CP_WAIT0(); }
        __syncthreads();

        bool act0 = (l + tb) >= 49;
        bool act1 = (l + tb) >= 33;
        if (act1) {
            const float* Bs = smf + GA_FLOATS + s * GB_STAGE;
            int fbase = tb + l + g;
            #pragma unroll
            for (int st = 0; st < 4; ++st) {
                int c = q4 + (ks * 4 + st) * 8;
                uint32_t A1[4];
                {
                    const float* ar = Ab + (fbase + 16) * AST;
                    A1[0] = __float_as_uint(ar[c]);
                    A1[1] = __float_as_uint(ar[8 * AST + c]);
                    A1[2] = __float_as_uint(ar[c + 4]);
                    A1[3] = __float_as_uint(ar[8 * AST + c + 4]);
                }
                uint32_t A0[4];
                if (act0) {
                    const float* ar = Ab + fbase * AST;
                    A0[0] = __float_as_uint(ar[c]);
                    A0[1] = __float_as_uint(ar[8 * AST + c]);
                    A0[2] = __float_as_uint(ar[c + 4]);
                    A0[3] = __float_as_uint(ar[8 * AST + c + 4]);
                }
                #pragma unroll
                for (int nt = 0; nt < 4; ++nt) {
                    int n = warpN * 32 + nt * 8 + g;
                    uint32_t bv0 = __float_as_uint(Bs[n * AST + c]);
                    uint32_t bv1 = __float_as_uint(Bs[n * AST + c + 4]);
                    if (act0) mma8(C[0][nt], A0, bv0, bv1);
                    mma8(C[1][nt], A1, bv0, bv1);
                }
            }
        }
        __syncthreads();
    }

    // epilogue: reduce C across ks pairs, then quad -> elp
    float* cred = smf + GA_FLOATS;           // 4 warps x 32 lanes x 33 = 4224 fl
    float* qsm  = cred + 4224;               // 128 floats
    int pid = warpM * 2 + warpN;

    if (ks == 1) {
        float* dst = cred + (pid * 32 + lane) * 33;
        #pragma unroll
        for (int mt = 0; mt < 2; ++mt)
            #pragma unroll
            for (int nt = 0; nt < 4; ++nt)
                #pragma unroll
                for (int i = 0; i < 4; ++i)
                    dst[mt * 16 + nt * 4 + i] = C[mt][nt][i];
    }
    __syncthreads();

    if (ks == 0) {
        const float* src = cred + (pid * 32 + lane) * 33;
        float ldk = d_logdet[k];
        const float* mpk = d_mp + k * CDIM;
        #pragma unroll
        for (int mt = 0; mt < 2; ++mt)
            #pragma unroll
            for (int nt = 0; nt < 4; ++nt)
                #pragma unroll
                for (int i = 0; i < 4; ++i)
                    C[mt][nt][i] += src[mt * 16 + nt * 4 + i];

        #pragma unroll
        for (int mt = 0; mt < 2; ++mt) {
            #pragma unroll
            for (int rh = 0; rh < 2; ++rh) {
                float sum = 0.f;
                #pragma unroll
                for (int nt = 0; nt < 4; ++nt) {
                    int col = warpN * 32 + nt * 8 + q4 * 2;
                    float v0 = C[mt][nt][rh * 2 + 0] - mpk[col];
                    float v1 = C[mt][nt][rh * 2 + 1] - mpk[col + 1];
                    sum += v0 * v0 + v1 * v1;
                }
                sum += __shfl_xor_sync(0xffffffffu, sum, 1);
                sum += __shfl_xor_sync(0xffffffffu, sum, 2);
                if (q4 == 0) {
                    int m = warpM * 32 + mt * 16 + rh * 8 + g;
                    qsm[m * 2 + warpN] = sum;
                }
            }
        }
    }
    __syncthreads();
    if (tid < 64) {
        int t = tid;
        float quad = qsm[t * 2] + qsm[t * 2 + 1];
        const float C_LOG2PI = 64.f * 1.8378770664093453f;
        d_elp[(((size_t)b) * 64 + t) * 8 + k] =
            -0.5f * (C_LOG2PI + quad) - d_logdet[k];
    }
}

// ---------------------------------------------------------------------------
__global__ void forward_kernel()
{
    __shared__ float lt_s[K_ST * K_ST];
    int tid = threadIdx.x;
    for (int i = tid; i < K_ST * K_ST; i += 32) lt_s[i] = d_lt[i];
    __syncthreads();
    int b = blockIdx.x * 32 + tid;
    if (b >= BATCH) return;

    const float* e = d_elp + (size_t)b * LSEQ * K_ST;
    float la[K_ST];
    for (int k = 0; k < K_ST; ++k) la[k] = d_linit[k] + e[k];
    for (int t = 1; t < LSEQ; ++t) {
        const float* et = e + t * K_ST;
        float nla[K_ST];
        #pragma unroll
        for (int k = 0; k < K_ST; ++k) {
            float m = -1e30f;
            #pragma unroll
            for (int j = 0; j < K_ST; ++j) m = fmaxf(m, la[j] + lt_s[j * K_ST + k]);
            float s = 0.f;
            #pragma unroll
            for (int j = 0; j < K_ST; ++j) s += __expf(la[j] + lt_s[j * K_ST + k] - m);
            nla[k] = m + __logf(s) + et[k];
        }
        #pragma unroll
        for (int k = 0; k < K_ST; ++k) la[k] = nla[k];
    }
    int arg = 0; float best = la[0];
    for (int k = 1; k < K_ST; ++k) if (la[k] > best) { best = la[k]; arg = k; }
    int s = d_next[arg];
    for (int p = 0; p < PRED; ++p) { d_states[b * PRED + p] = s; s = d_next[s]; }
}

// ---------------------------------------------------------------------------
__global__ void group_kernel()
{
    __shared__ int cnt[K_ST], off[K_ST + 1], cur[K_ST];
    int tid = threadIdx.x;
    if (tid == 0) d_psync = 0u;
    if (tid < K_ST) { cnt[tid] = 0; cur[tid] = 0; }
    __syncthreads();
    int g = d_states[tid * PRED];
    atomicAdd(&cnt[g], 1);
    __syncthreads();
    if (tid == 0) {
        off[0] = 0;
        for (int i = 0; i < K_ST; ++i) off[i + 1] = off[i] + cnt[i];
    }
    __syncthreads();
    int pos = off[g] + atomicAdd(&cur[g], 1);
    d_perm[pos] = tid;
    if (tid < K_ST) {
        d_gcnt[tid] = cnt[tid];
        d_goff[tid] = off[tid];
        int s = tid;
        for (int p = 0; p < PRED; ++p) { d_chain[tid * PRED + p] = s; s = d_next[s]; }
    }
}

// ---------------------------------------------------------------------------
#define PA_FLOATS (2 * 2 * 32 * PST)    // 8704
#define PB_STAGE  (2 * 64 * PST)        // 8704
#define PSMEM_BYTES ((PA_FLOATS + 2 * PB_STAGE) * 4)

__device__ __forceinline__ void p_fill2(int aframe, int bchunk, int stage, int k,
                                        int goff, int cnt, int row0,
                                        uint32_t sb, int tid)
{
    for (int idx = tid; idx < 1024; idx += 256) {
        int part = idx >> 9, i = (idx >> 4) & 31, q = idx & 15;
        int r = row0 + i; if (r >= cnt) r = row0;
        int b = d_perm[goff + r];
        const float* base = part ? d_winlo : d_winhi;
        const float* src = base + ((size_t)b * 80 + aframe) * 64 + q * 4;
        cpa16(sb + (stage * (2 * 32 * PST) + part * (32 * PST) + i * PST) * 4 + q * 16, src);
    }
    for (int idx = tid; idx < 2048; idx += 256) {
        int part = idx >> 10, n = (idx >> 4) & 63, q = idx & 15;
        const float* base = part ? d_Wplo : d_Wphi;
        const float* src = base + ((size_t)(k * 64 + n)) * FDIM + bchunk * 64 + q * 4;
        cpa16(sb + (PA_FLOATS + stage * PB_STAGE + part * (64 * PST) + n * PST) * 4 + q * 16, src);
    }
    CP_COMMIT();
}

__device__ __forceinline__ void p_mma(float C[2][4], int s, int warpM, int warpN,
                                      int gg, int q4)
{
    const float* Ahi = smf + s * (2 * 32 * PST);
    const float* Alo = Ahi + 32 * PST;
    const float* Bhi = smf + PA_FLOATS + s * PB_STAGE;
    const float* Blo = Bhi + 64 * PST;
    int r0 = warpM * 16 + gg;

    #pragma unroll
    for (int st = 0; st < 8; ++st) {
        int c = q4 + st * 8;
        uint32_t ah[4], al[4];
        ah[0] = __float_as_uint(Ahi[r0 * PST + c]);
        ah[1] = __float_as_uint(Ahi[(r0 + 8) * PST + c]);
        ah[2] = __float_as_uint(Ahi[r0 * PST + c + 4]);
        ah[3] = __float_as_uint(Ahi[(r0 + 8) * PST + c + 4]);
        al[0] = __float_as_uint(Alo[r0 * PST + c]);
        al[1] = __float_as_uint(Alo[(r0 + 8) * PST + c]);
        al[2] = __float_as_uint(Alo[r0 * PST + c + 4]);
        al[3] = __float_as_uint(Alo[(r0 + 8) * PST + c + 4]);
        #pragma unroll
        for (int nt = 0; nt < 2; ++nt) {
            int n = warpN * 16 + nt * 8 + gg;
            uint32_t bh0 = __float_as_uint(Bhi[n * PST + c]);
            uint32_t bh1 = __float_as_uint(Bhi[n * PST + c + 4]);
            uint32_t bl0 = __float_as_uint(Blo[n * PST + c]);
            uint32_t bl1 = __float_as_uint(Blo[n * PST + c + 4]);
            mma8(C[nt], ah, bh0, bh1);
            mma8(C[nt], ah, bl0, bl1);
            mma8(C[nt], al, bh0, bh1);
        }
    }
}

__global__ __launch_bounds__(256, 2) void pred_em()
{
    int p = blockIdx.y;
    int g = blockIdx.x >> 4, tile = blockIdx.x & 15;
    int cnt = d_gcnt[g];
    int row0 = tile * 32;
    if (row0 >= cnt) return;
    int goff = d_goff[g];
    int k = d_chain[g * PRED + p];

    uint32_t sb = smem_u32(smf);
    int tid = threadIdx.x;
    int wid = tid >> 5, lane = tid & 31;
    int gg = lane >> 2, q4 = lane & 3;
    int warpM = wid >> 2, warpN = wid & 3;

    float C[2][4];
    #pragma unroll
    for (int nt = 0; nt < 2; ++nt)
        #pragma unroll
        for (int i = 0; i < 4; ++i) C[nt][i] = 0.f;

    int nchunks = 64 - p;
    p_fill2(p, 0, 0, k, goff, cnt, row0, sb, tid);
    for (int j = 0; j < nchunks; ++j) {
        int s = j & 1;
        if (j < nchunks - 1) {
            p_fill2(p + j + 1, j + 1, s ^ 1, k, goff, cnt, row0, sb, tid);
            CP_WAIT1();
        } else CP_WAIT0();
        __syncthreads();
        p_mma(C, s, warpM, warpN, gg, q4);
        __syncthreads();
    }

    #pragma unroll
    for (int nt = 0; nt < 2; ++nt)
        #pragma unroll
        for (int rh = 0; rh < 2; ++rh) {
            int m = warpM * 16 + rh * 8 + gg;
            int r = row0 + m;
            if (r < cnt) {
                int b = d_perm[goff + r];
                #pragma unroll
                for (int cc = 0; cc < 2; ++cc) {
                    int col = warpN * 16 + nt * 8 + q4 * 2 + cc;
                    d_yem[((size_t)b * PRED + p) * CDIM + col] = C[nt][rh * 2 + cc];
                }
            }
        }
}

// ---------------------------------------------------------------------------
__global__ __launch_bounds__(256, 2) void pred_rec_persist(
    const float* __restrict__ means, float* __restrict__ out)
{
    int bid = blockIdx.x;
    int g = bid >> 4, tile = bid & 15;
    int goff = d_goff[g];
    int cnt = d_gcnt[g];
    int row0 = tile * 32;
    bool active = (row0 < cnt);

    uint32_t sb = smem_u32(smf);
    int tid = threadIdx.x;
    int wid = tid >> 5, lane = tid & 31;
    int gg = lane >> 2, q4 = lane & 3;
    int warpM = wid >> 2, warpN = wid & 3;

    for (int p = 0; p < PRED; ++p) {
        int k = d_chain[g * PRED + p];

        float C[2][4];
        #pragma unroll
        for (int nt = 0; nt < 2; ++nt)
            #pragma unroll
            for (int i = 0; i < 4; ++i) C[nt][i] = 0.f;

        if (active && p > 0) {
            p_fill2(64, 64 - p, 0, k, goff, cnt, row0, sb, tid);
            for (int q = 0; q < p; ++q) {
                int s = q & 1;
                if (q < p - 1) {
                    p_fill2(64 + q + 1, 64 - p + q + 1, s ^ 1, k, goff, cnt, row0, sb, tid);
                    CP_WAIT1();
                } else CP_WAIT0();
                __syncthreads();
                p_mma(C, s, warpM, warpN, gg, q4);
                __syncthreads();
            }
        }

        if (active) {
            #pragma unroll
            for (int nt = 0; nt < 2; ++nt)
                #pragma unroll
                for (int rh = 0; rh < 2; ++rh) {
                    int m = warpM * 16 + rh * 8 + gg;
                    int r = row0 + m;
                    if (r < cnt) {
                        int b = d_perm[goff + r];
                        #pragma unroll
                        for (int cc = 0; cc < 2; ++cc) {
                            int col = warpN * 16 + nt * 8 + q4 * 2 + cc;
                            float v = C[nt][rh * 2 + cc]
                                    + d_yem[((size_t)b * PRED + p) * CDIM + col]
                                    + means[k * CDIM + col];
                            out[((size_t)b * PRED + p) * CDIM + col] = v;
                            float h = tf32r(v);
                            d_winhi[((size_t)b * 80 + 64 + p) * 64 + col] = h;
                            d_winlo[((size_t)b * 80 + 64 + p) * 64 + col] = tf32r(v - h);
                        }
                    }
                }
        }

        if (p < PRED - 1) {
            __threadfence();
            __syncthreads();
            if (tid == 0) {
                atomicAdd(&d_psync, 1u);
                unsigned target = (unsigned)gridDim.x * (unsigned)(p + 1);
                unsigned v;
                do {
                    asm volatile("ld.acquire.gpu.u32 %0, [%1];"
                                 : "=r"(v) : "l"(&d_psync));
                    if (v < target) __nanosleep(64);
                } while (v < target);
            }
            __syncthreads();
            __threadfence();
        }
    }
}

// ---------------------------------------------------------------------------
extern "C" void kernel_launch(void* const* d_in, const int* in_sizes, int n_in,
                              void* d_out, int out_size)
{
    const float* em    = (const float*)d_in[0];
    const float* tm    = (const float*)d_in[1];
    const float* initd = (const float*)d_in[2];
    const float* means = (const float*)d_in[3];
    const float* cchol = (const float*)d_in[4];
    const float* W     = (const float*)d_in[5];
    float* out = (float*)d_out;

    cudaFuncSetAttribute(gemm_elp, cudaFuncAttributeMaxDynamicSharedMemorySize,
                         GSMEM_BYTES);
    cudaFuncSetAttribute(pred_em, cudaFuncAttributeMaxDynamicSharedMemorySize,
                         PSMEM_BYTES);
    cudaFuncSetAttribute(pred_rec_persist, cudaFuncAttributeMaxDynamicSharedMemorySize,
                         PSMEM_BYTES);

    prep_small<<<1, 32>>>(tm, initd);                           // 1
    prep_chol<<<8, 256>>>(cchol, means);                        // 2
    wp2_kernel<<<dim3(64, 8), 256>>>(W);                        // 3
    gemm_elp<<<dim3(512, 8), 256, GSMEM_BYTES>>>(em);           // 4 <- ncu slot
    forward_kernel<<<16, 32>>>();                               // 5
    wsplit_kernel<<<2048, 256>>>(W);                            // 6
    win_init_kernel<<<512, 256>>>(em);                          // 7
    group_kernel<<<1, 512>>>();                                 // 8
    pred_em<<<dim3(128, 16), 256, PSMEM_BYTES>>>();             // 9
    pred_rec_persist<<<128, 256, PSMEM_BYTES>>>(means, out);    // 10
}

// round 13
// speedup vs baseline: 1.3917x; 1.3737x over previous
#include <cuda_runtime.h>
#include <cuda_bf16.h>
#include <math.h>
#include <stdint.h>

// ---------------------------------------------------------------------------
// LinearAutoregressiveHMM — round 13:
//  * elp GEMM switched tf32 m16n8k8 -> bf16 m16n8k16: MMA + LDS instruction
//    counts halved (the measured binding constraint was aux-instr per HMMA).
//    elp only feeds an argmax chain -> bf16 is precision-safe there.
//  * pred path unchanged (tf32 3-term, full output precision).
// ---------------------------------------------------------------------------

#define K_ST   8
#define LSEQ   64
#define CDIM   64
#define BATCH  512
#define PRED   16
#define FDIM   4096
#define BST    72            // bf16 smem row stride (144 B): bank-distinct frags
#define PST    68

// static scratch
__device__ __nv_bfloat16 d_Wnb[K_ST * CDIM * FDIM];   // bf16(-(IC@W))
__device__ __nv_bfloat16 d_ICb[K_ST * CDIM * CDIM];   // bf16(IC)
__device__ float d_IC  [K_ST * CDIM * CDIM];
__device__ float d_mp  [K_ST * CDIM];
__device__ float d_logdet[K_ST];
__device__ float d_lt  [K_ST * K_ST];
__device__ float d_linit[K_ST];
__device__ int   d_next[K_ST];
__device__ float d_elp [BATCH * LSEQ * K_ST];
__device__ int   d_states[BATCH * PRED];
__device__ float d_Wphi[K_ST * CDIM * FDIM];
__device__ float d_Wplo[K_ST * CDIM * FDIM];
__device__ float d_winhi[BATCH * 80 * CDIM];
__device__ float d_winlo[BATCH * 80 * CDIM];
__device__ int   d_perm[BATCH];
__device__ int   d_goff[K_ST];
__device__ int   d_gcnt[K_ST];
__device__ int   d_chain[K_ST * PRED];
__device__ float d_yem[BATCH * PRED * CDIM];
__device__ unsigned int d_psync;

// ---------------------------------------------------------------------------
__device__ __forceinline__ float tf32r(float x) {
    uint32_t u;
    asm("cvt.rna.tf32.f32 %0, %1;" : "=r"(u) : "f"(x));
    return __uint_as_float(u);
}
__device__ __forceinline__ uint32_t smem_u32(const void* p) {
    uint32_t a;
    asm("{ .reg .u64 t; cvta.to.shared.u64 t, %1; cvt.u32.u64 %0, t; }"
        : "=r"(a) : "l"(p));
    return a;
}
__device__ __forceinline__ void cpa16(uint32_t dst, const void* src) {
    asm volatile("cp.async.cg.shared.global [%0], [%1], 16;" :: "r"(dst), "l"(src));
}
#define CP_COMMIT() asm volatile("cp.async.commit_group;" ::: "memory")
#define CP_WAIT1()  asm volatile("cp.async.wait_group 1;" ::: "memory")
#define CP_WAIT0()  asm volatile("cp.async.wait_group 0;" ::: "memory")

__device__ __forceinline__ void mma8(float c[4], const uint32_t a[4],
                                     uint32_t b0, uint32_t b1) {
    asm volatile(
        "mma.sync.aligned.m16n8k8.row.col.f32.tf32.tf32.f32 "
        "{%0,%1,%2,%3},{%4,%5,%6,%7},{%8,%9},{%0,%1,%2,%3};"
        : "+f"(c[0]), "+f"(c[1]), "+f"(c[2]), "+f"(c[3])
        : "r"(a[0]), "r"(a[1]), "r"(a[2]), "r"(a[3]), "r"(b0), "r"(b1));
}
__device__ __forceinline__ void mma16b(float c[4], const uint32_t a[4],
                                       uint32_t b0, uint32_t b1) {
    asm volatile(
        "mma.sync.aligned.m16n8k16.row.col.f32.bf16.bf16.f32 "
        "{%0,%1,%2,%3},{%4,%5,%6,%7},{%8,%9},{%0,%1,%2,%3};"
        : "+f"(c[0]), "+f"(c[1]), "+f"(c[2]), "+f"(c[3])
        : "r"(a[0]), "r"(a[1]), "r"(a[2]), "r"(a[3]), "r"(b0), "r"(b1));
}

// ---------------------------------------------------------------------------
__global__ void prep_small(const float* __restrict__ tm,
                           const float* __restrict__ initd)
{
    int tid = threadIdx.x;
    if (tid < K_ST) {
        float row[K_ST];
        float m = -1e30f;
        for (int j = 0; j < K_ST; ++j) { row[j] = tm[tid * K_ST + j]; m = fmaxf(m, row[j]); }
        float s = 0.f;
        for (int j = 0; j < K_ST; ++j) s += expf(row[j] - m);
        float lse = m + logf(s);
        for (int j = 0; j < K_ST; ++j)
            d_lt[tid * K_ST + j] = logf(expf(row[j] - lse) + 1e-8f);
        int arg = 0; float best = row[0];
        for (int j = 1; j < K_ST; ++j) if (row[j] > best) { best = row[j]; arg = j; }
        d_next[tid] = arg;
    }
    if (tid == 8) {
        float m = -1e30f;
        for (int j = 0; j < K_ST; ++j) m = fmaxf(m, initd[j]);
        float s = 0.f;
        for (int j = 0; j < K_ST; ++j) s += expf(initd[j] - m);
        float lse = m + logf(s);
        for (int j = 0; j < K_ST; ++j) d_linit[j] = initd[j] - lse;
    }
}

// ---------------------------------------------------------------------------
__global__ void prep_chol(const float* __restrict__ cchol,
                          const float* __restrict__ means)
{
    __shared__ float T[CDIM * CDIM];
    __shared__ float Cv[CDIM * CDIM];
    int tid = threadIdx.x;
    int k = blockIdx.x;

    for (int idx = tid; idx < CDIM * CDIM; idx += 256) {
        int i = idx >> 6, j = idx & 63;
        float v = cchol[k * CDIM * CDIM + idx];
        T[idx] = (j > i) ? 0.f : (j == i ? expf(v) : v);
    }
    __syncthreads();
    for (int idx = tid; idx < CDIM * CDIM; idx += 256) {
        int i = idx >> 6, j = idx & 63;
        int mmax = (i < j) ? i : j;
        float s = (i == j) ? 1e-6f : 0.f;
        for (int m = 0; m <= mmax; ++m) s += T[i * 64 + m] * T[j * 64 + m];
        Cv[idx] = s;
    }
    __syncthreads();
    for (int c = 0; c < CDIM; ++c) {
        if (tid == 0) Cv[c * 64 + c] = sqrtf(Cv[c * 64 + c]);
        __syncthreads();
        float dinv = 1.f / Cv[c * 64 + c];
        for (int i = c + 1 + tid; i < CDIM; i += 256) Cv[i * 64 + c] *= dinv;
        __syncthreads();
        for (int idx = tid; idx < CDIM * CDIM; idx += 256) {
            int i = idx >> 6, m = idx & 63;
            if (i > c && m > c && m <= i)
                Cv[i * 64 + m] -= Cv[i * 64 + c] * Cv[m * 64 + c];
        }
        __syncthreads();
    }
    if (tid == 0) {
        float s = 0.f;
        for (int i = 0; i < CDIM; ++i) s += logf(Cv[i * 64 + i]);
        d_logdet[k] = s;
    }
    for (int idx = tid; idx < CDIM * CDIM; idx += 256) T[idx] = 0.f;
    __syncthreads();
    if (tid < CDIM) {
        int c = tid;
        T[c * 64 + c] = 1.f / Cv[c * 64 + c];
        for (int i = c + 1; i < CDIM; ++i) {
            float s = 0.f;
            for (int m = c; m < i; ++m) s += Cv[i * 64 + m] * T[m * 64 + c];
            T[i * 64 + c] = -s / Cv[i * 64 + i];
        }
    }
    __syncthreads();
    for (int idx = tid; idx < CDIM * CDIM; idx += 256) {
        float v = T[idx];
        d_IC[k * CDIM * CDIM + idx] = v;
        d_ICb[k * CDIM * CDIM + idx] = __float2bfloat16_rn(v);
    }
    if (tid < CDIM) {
        float s = 0.f;
        for (int j = 0; j < CDIM; ++j) s += T[tid * 64 + j] * means[k * CDIM + j];
        d_mp[k * CDIM + tid] = s;
    }
}

// ---------------------------------------------------------------------------
__global__ __launch_bounds__(256) void wp2_kernel(const float* __restrict__ W)
{
    __shared__ float Wt[64 * 65];
    __shared__ float ICs[64 * 65];
    int f0 = blockIdx.x * 64, k = blockIdx.y;
    int tid = threadIdx.x;

    for (int idx = tid; idx < 4096; idx += 256) {
        int c = idx >> 6, c2 = idx & 63;
        ICs[c * 65 + c2] = d_IC[k * 4096 + c * 64 + c2];
        Wt[c * 65 + c2] = W[(size_t)k * CDIM * FDIM + c * FDIM + f0 + c2];
    }
    __syncthreads();

    int fi = tid & 63, cq = tid >> 6;
    #pragma unroll 4
    for (int t = 0; t < 16; ++t) {
        int c = cq * 16 + t;
        float s = 0.f;
        #pragma unroll 16
        for (int c2 = 0; c2 < 64; ++c2)
            s += ICs[c * 65 + c2] * Wt[c2 * 65 + fi];
        d_Wnb[((size_t)(k * 64 + c)) * FDIM + f0 + fi] = __float2bfloat16_rn(-s);
    }
}

// ---------------------------------------------------------------------------
__global__ void wsplit_kernel(const float* __restrict__ W)
{
    int i = blockIdx.x * 1024 + threadIdx.x * 4;
    #pragma unroll
    for (int j = 0; j < 4; ++j) {
        float v = W[i + j];
        float h = tf32r(v);
        d_Wphi[i + j] = h;
        d_Wplo[i + j] = tf32r(v - h);
    }
}

__global__ void win_init_kernel(const float* __restrict__ em)
{
    int b = blockIdx.x;
    for (int i = threadIdx.x; i < FDIM; i += 256) {
        float v = em[(size_t)b * FDIM + i];
        float h = tf32r(v);
        d_winhi[(size_t)b * 5120 + i] = h;
        d_winlo[(size_t)b * 5120 + i] = tf32r(v - h);
    }
}

// ---------------------------------------------------------------------------
// elp GEMM, bf16 m16n8k16. CTA = (2 batches, state k), 8 warps warpM(4)xwarpN(2).
// A panel: 2 x 128 rows x BST bf16. B: 64 x BST bf16, double-buffered.
// smem = 2*128*144 + 2*64*144 = 55296 B -> 3 CTAs/SM.
// ---------------------------------------------------------------------------
#define GA_HALF   (128 * BST)                 // bf16 elems per batch panel
#define GB_STAGE  (64 * BST)                  // bf16 elems per B stage
#define GSMEM_BYTES ((2 * GA_HALF + 2 * GB_STAGE) * 2)

extern __shared__ float smf[];

__device__ __forceinline__ void g_fill_B(int l, int stage, int k,
                                         uint32_t sb, int tid)
{
    uint32_t base = sb + (2 * GA_HALF + stage * GB_STAGE) * 2;
    for (int idx = tid; idx < 512; idx += 256) {
        int n = idx >> 3, q = idx & 7;
        const __nv_bfloat16* src = (l < 64)
            ? d_Wnb + ((size_t)(k * 64 + n)) * FDIM + l * 64 + q * 8
            : d_ICb + (k * 64 + n) * 64 + q * 8;
        cpa16(base + n * (BST * 2) + q * 16, src);
    }
    CP_COMMIT();
}

__global__ __launch_bounds__(256) void gemm_elp(const float* __restrict__ em)
{
    uint32_t sb = smem_u32(smf);
    __nv_bfloat16* smb = (__nv_bfloat16*)smf;
    int tid = threadIdx.x;
    int wid = tid >> 5, lane = tid & 31;
    int g = lane >> 2, q4 = lane & 3;
    int bx = blockIdx.x, k = blockIdx.y;
    int b0 = bx * 2;

    g_fill_B(0, 0, k, sb, tid);

    // A panel: rows 0..63 zero (full BST width), rows 64..127 = em (bf16)
    for (int idx = tid; idx < 2 * 64 * 9; idx += 256) {
        int b = idx / (64 * 9); int rem = idx - b * 64 * 9;
        int r = rem / 9, q = rem - r * 9;
        *(uint4*)((char*)(smb + b * GA_HALF + r * BST) + q * 16) =
            make_uint4(0, 0, 0, 0);
    }
    for (int idx = tid; idx < 2048; idx += 256) {
        int b = idx >> 10; int t = (idx >> 4) & 63; int q = idx & 15;
        float4 v = *(const float4*)(em + (((size_t)(b0 + b)) * 64 + t) * 64 + q * 4);
        uint32_t w0 = (uint32_t)__bfloat16_as_ushort(__float2bfloat16_rn(v.x)) |
                      ((uint32_t)__bfloat16_as_ushort(__float2bfloat16_rn(v.y)) << 16);
        uint32_t w1 = (uint32_t)__bfloat16_as_ushort(__float2bfloat16_rn(v.z)) |
                      ((uint32_t)__bfloat16_as_ushort(__float2bfloat16_rn(v.w)) << 16);
        *(uint2*)(smb + b * GA_HALF + (64 + t) * BST + q * 4) = make_uint2(w0, w1);
    }

    int warpM = wid >> 1, warpN = wid & 1;
    int bp = warpM >> 1;
    int tb = (warpM & 1) * 32;
    const __nv_bfloat16* Ab = smb + bp * GA_HALF;

    float C[2][4][4];
    #pragma unroll
    for (int mt = 0; mt < 2; ++mt)
        #pragma unroll
        for (int nt = 0; nt < 4; ++nt)
            #pragma unroll
            for (int i = 0; i < 4; ++i) C[mt][nt][i] = 0.f;

    for (int l = 0; l <= 64; ++l) {
        int s = l & 1;
        if (l < 64) { g_fill_B(l + 1, s ^ 1, k, sb, tid); CP_WAIT1(); }
        else        { CP_WAIT0(); }
        __syncthreads();

        bool act0 = (l + tb) >= 49;
        bool act1 = (l + tb) >= 33;
        if (act1) {
            const __nv_bfloat16* Bs = smb + 2 * GA_HALF + s * GB_STAGE;
            int fbase = tb + l + g;
            #pragma unroll
            for (int st = 0; st < 4; ++st) {
                int c2 = st * 16 + 2 * q4;
                uint32_t A1[4];
                {
                    const __nv_bfloat16* ar = Ab + (fbase + 16) * BST + c2;
                    A1[0] = *(const uint32_t*)ar;
                    A1[1] = *(const uint32_t*)(ar + 8 * BST);
                    A1[2] = *(const uint32_t*)(ar + 8);
                    A1[3] = *(const uint32_t*)(ar + 8 * BST + 8);
                }
                uint32_t A0[4];
                if (act0) {
                    const __nv_bfloat16* ar = Ab + fbase * BST + c2;
                    A0[0] = *(const uint32_t*)ar;
                    A0[1] = *(const uint32_t*)(ar + 8 * BST);
                    A0[2] = *(const uint32_t*)(ar + 8);
                    A0[3] = *(const uint32_t*)(ar + 8 * BST + 8);
                }
                #pragma unroll
                for (int nt = 0; nt < 4; ++nt) {
                    int n = warpN * 32 + nt * 8 + g;
                    uint32_t bv0 = *(const uint32_t*)(Bs + n * BST + c2);
                    uint32_t bv1 = *(const uint32_t*)(Bs + n * BST + c2 + 8);
                    if (act0) mma16b(C[0][nt], A0, bv0, bv1);
                    mma16b(C[1][nt], A1, bv0, bv1);
                }
            }
        }
        __syncthreads();
    }

    // epilogue: quad = sum_cols (D - mp)^2 -> elp  (reuse B area)
    float* qsm = (float*)(smb + 2 * GA_HALF);
    float ldk = d_logdet[k];
    const float* mpk = d_mp + k * CDIM;

    #pragma unroll
    for (int mt = 0; mt < 2; ++mt) {
        #pragma unroll
        for (int rh = 0; rh < 2; ++rh) {
            float sum = 0.f;
            #pragma unroll
            for (int nt = 0; nt < 4; ++nt) {
                int col = warpN * 32 + nt * 8 + q4 * 2;
                float v0 = C[mt][nt][rh * 2 + 0] - mpk[col];
                float v1 = C[mt][nt][rh * 2 + 1] - mpk[col + 1];
                sum += v0 * v0 + v1 * v1;
            }
            sum += __shfl_xor_sync(0xffffffffu, sum, 1);
            sum += __shfl_xor_sync(0xffffffffu, sum, 2);
            if (q4 == 0) {
                int m = warpM * 32 + mt * 16 + rh * 8 + g;
                qsm[m * 2 + warpN] = sum;
            }
        }
    }
    __syncthreads();
    if (tid < 128) {
        int m = tid;
        float quad = qsm[m * 2] + qsm[m * 2 + 1];
        int b = b0 + (m >= 64), t = m & 63;
        const float C_LOG2PI = 64.f * 1.8378770664093453f;
        d_elp[(((size_t)b) * 64 + t) * 8 + k] = -0.5f * (C_LOG2PI + quad) - ldk;
    }
}

// ---------------------------------------------------------------------------
__global__ void forward_kernel()
{
    __shared__ float lt_s[K_ST * K_ST];
    int tid = threadIdx.x;
    for (int i = tid; i < K_ST * K_ST; i += 32) lt_s[i] = d_lt[i];
    __syncthreads();
    int b = blockIdx.x * 32 + tid;
    if (b >= BATCH) return;

    const float* e = d_elp + (size_t)b * LSEQ * K_ST;
    float la[K_ST];
    for (int k = 0; k < K_ST; ++k) la[k] = d_linit[k] + e[k];
    for (int t = 1; t < LSEQ; ++t) {
        const float* et = e + t * K_ST;
        float nla[K_ST];
        #pragma unroll
        for (int k = 0; k < K_ST; ++k) {
            float m = -1e30f;
            #pragma unroll
            for (int j = 0; j < K_ST; ++j) m = fmaxf(m, la[j] + lt_s[j * K_ST + k]);
            float s = 0.f;
            #pragma unroll
            for (int j = 0; j < K_ST; ++j) s += __expf(la[j] + lt_s[j * K_ST + k] - m);
            nla[k] = m + __logf(s) + et[k];
        }
        #pragma unroll
        for (int k = 0; k < K_ST; ++k) la[k] = nla[k];
    }
    int arg = 0; float best = la[0];
    for (int k = 1; k < K_ST; ++k) if (la[k] > best) { best = la[k]; arg = k; }
    int s = d_next[arg];
    for (int p = 0; p < PRED; ++p) { d_states[b * PRED + p] = s; s = d_next[s]; }
}

// ---------------------------------------------------------------------------
__global__ void group_kernel()
{
    __shared__ int cnt[K_ST], off[K_ST + 1], cur[K_ST];
    int tid = threadIdx.x;
    if (tid == 0) d_psync = 0u;
    if (tid < K_ST) { cnt[tid] = 0; cur[tid] = 0; }
    __syncthreads();
    int g = d_states[tid * PRED];
    atomicAdd(&cnt[g], 1);
    __syncthreads();
    if (tid == 0) {
        off[0] = 0;
        for (int i = 0; i < K_ST; ++i) off[i + 1] = off[i] + cnt[i];
    }
    __syncthreads();
    int pos = off[g] + atomicAdd(&cur[g], 1);
    d_perm[pos] = tid;
    if (tid < K_ST) {
        d_gcnt[tid] = cnt[tid];
        d_goff[tid] = off[tid];
        int s = tid;
        for (int p = 0; p < PRED; ++p) { d_chain[tid * PRED + p] = s; s = d_next[s]; }
    }
}

// ---------------------------------------------------------------------------
#define PA_FLOATS (2 * 2 * 32 * PST)    // 8704
#define PB_STAGE  (2 * 64 * PST)        // 8704
#define PSMEM_BYTES ((PA_FLOATS + 2 * PB_STAGE) * 4)

__device__ __forceinline__ void p_fill2(int aframe, int bchunk, int stage, int k,
                                        int goff, int cnt, int row0,
                                        uint32_t sb, int tid)
{
    for (int idx = tid; idx < 1024; idx += 256) {
        int part = idx >> 9, i = (idx >> 4) & 31, q = idx & 15;
        int r = row0 + i; if (r >= cnt) r = row0;
        int b = d_perm[goff + r];
        const float* base = part ? d_winlo : d_winhi;
        const float* src = base + ((size_t)b * 80 + aframe) * 64 + q * 4;
        cpa16(sb + (stage * (2 * 32 * PST) + part * (32 * PST) + i * PST) * 4 + q * 16, src);
    }
    for (int idx = tid; idx < 2048; idx += 256) {
        int part = idx >> 10, n = (idx >> 4) & 63, q = idx & 15;
        const float* base = part ? d_Wplo : d_Wphi;
        const float* src = base + ((size_t)(k * 64 + n)) * FDIM + bchunk * 64 + q * 4;
        cpa16(sb + (PA_FLOATS + stage * PB_STAGE + part * (64 * PST) + n * PST) * 4 + q * 16, src);
    }
    CP_COMMIT();
}

__device__ __forceinline__ void p_mma(float C[2][4], int s, int warpM, int warpN,
                                      int gg, int q4)
{
    const float* Ahi = smf + s * (2 * 32 * PST);
    const float* Alo = Ahi + 32 * PST;
    const float* Bhi = smf + PA_FLOATS + s * PB_STAGE;
    const float* Blo = Bhi + 64 * PST;
    int r0 = warpM * 16 + gg;

    #pragma unroll
    for (int st = 0; st < 8; ++st) {
        int c = q4 + st * 8;
        uint32_t ah[4], al[4];
        ah[0] = __float_as_uint(Ahi[r0 * PST + c]);
        ah[1] = __float_as_uint(Ahi[(r0 + 8) * PST + c]);
        ah[2] = __float_as_uint(Ahi[r0 * PST + c + 4]);
        ah[3] = __float_as_uint(Ahi[(r0 + 8) * PST + c + 4]);
        al[0] = __float_as_uint(Alo[r0 * PST + c]);
        al[1] = __float_as_uint(Alo[(r0 + 8) * PST + c]);
        al[2] = __float_as_uint(Alo[r0 * PST + c + 4]);
        al[3] = __float_as_uint(Alo[(r0 + 8) * PST + c + 4]);
        #pragma unroll
        for (int nt = 0; nt < 2; ++nt) {
            int n = warpN * 16 + nt * 8 + gg;
            uint32_t bh0 = __float_as_uint(Bhi[n * PST + c]);
            uint32_t bh1 = __float_as_uint(Bhi[n * PST + c + 4]);
            uint32_t bl0 = __float_as_uint(Blo[n * PST + c]);
            uint32_t bl1 = __float_as_uint(Blo[n * PST + c + 4]);
            mma8(C[nt], ah, bh0, bh1);
            mma8(C[nt], ah, bl0, bl1);
            mma8(C[nt], al, bh0, bh1);
        }
    }
}

__global__ __launch_bounds__(256, 2) void pred_em()
{
    int p = blockIdx.y;
    int g = blockIdx.x >> 4, tile = blockIdx.x & 15;
    int cnt = d_gcnt[g];
    int row0 = tile * 32;
    if (row0 >= cnt) return;
    int goff = d_goff[g];
    int k = d_chain[g * PRED + p];

    uint32_t sb = smem_u32(smf);
    int tid = threadIdx.x;
    int wid = tid >> 5, lane = tid & 31;
    int gg = lane >> 2, q4 = lane & 3;
    int warpM = wid >> 2, warpN = wid & 3;

    float C[2][4];
    #pragma unroll
    for (int nt = 0; nt < 2; ++nt)
        #pragma unroll
        for (int i = 0; i < 4; ++i) C[nt][i] = 0.f;

    int nchunks = 64 - p;
    p_fill2(p, 0, 0, k, goff, cnt, row0, sb, tid);
    for (int j = 0; j < nchunks; ++j) {
        int s = j & 1;
        if (j < nchunks - 1) {
            p_fill2(p + j + 1, j + 1, s ^ 1, k, goff, cnt, row0, sb, tid);
            CP_WAIT1();
        } else CP_WAIT0();
        __syncthreads();
        p_mma(C, s, warpM, warpN, gg, q4);
        __syncthreads();
    }

    #pragma unroll
    for (int nt = 0; nt < 2; ++nt)
        #pragma unroll
        for (int rh = 0; rh < 2; ++rh) {
            int m = warpM * 16 + rh * 8 + gg;
            int r = row0 + m;
            if (r < cnt) {
                int b = d_perm[goff + r];
                #pragma unroll
                for (int cc = 0; cc < 2; ++cc) {
                    int col = warpN * 16 + nt * 8 + q4 * 2 + cc;
                    d_yem[((size_t)b * PRED + p) * CDIM + col] = C[nt][rh * 2 + cc];
                }
            }
        }
}

// ---------------------------------------------------------------------------
__global__ __launch_bounds__(256, 2) void pred_rec_persist(
    const float* __restrict__ means, float* __restrict__ out)
{
    int bid = blockIdx.x;
    int g = bid >> 4, tile = bid & 15;
    int goff = d_goff[g];
    int cnt = d_gcnt[g];
    int row0 = tile * 32;
    bool active = (row0 < cnt);

    uint32_t sb = smem_u32(smf);
    int tid = threadIdx.x;
    int wid = tid >> 5, lane = tid & 31;
    int gg = lane >> 2, q4 = lane & 3;
    int warpM = wid >> 2, warpN = wid & 3;

    for (int p = 0; p < PRED; ++p) {
        int k = d_chain[g * PRED + p];

        float C[2][4];
        #pragma unroll
        for (int nt = 0; nt < 2; ++nt)
            #pragma unroll
            for (int i = 0; i < 4; ++i) C[nt][i] = 0.f;

        if (active && p > 0) {
            p_fill2(64, 64 - p, 0, k, goff, cnt, row0, sb, tid);
            for (int q = 0; q < p; ++q) {
                int s = q & 1;
                if (q < p - 1) {
                    p_fill2(64 + q + 1, 64 - p + q + 1, s ^ 1, k, goff, cnt, row0, sb, tid);
                    CP_WAIT1();
                } else CP_WAIT0();
                __syncthreads();
                p_mma(C, s, warpM, warpN, gg, q4);
                __syncthreads();
            }
        }

        if (active) {
            #pragma unroll
            for (int nt = 0; nt < 2; ++nt)
                #pragma unroll
                for (int rh = 0; rh < 2; ++rh) {
                    int m = warpM * 16 + rh * 8 + gg;
                    int r = row0 + m;
                    if (r < cnt) {
                        int b = d_perm[goff + r];
                        #pragma unroll
                        for (int cc = 0; cc < 2; ++cc) {
                            int col = warpN * 16 + nt * 8 + q4 * 2 + cc;
                            float v = C[nt][rh * 2 + cc]
                                    + d_yem[((size_t)b * PRED + p) * CDIM + col]
                                    + means[k * CDIM + col];
                            out[((size_t)b * PRED + p) * CDIM + col] = v;
                            float h = tf32r(v);
                            d_winhi[((size_t)b * 80 + 64 + p) * 64 + col] = h;
                            d_winlo[((size_t)b * 80 + 64 + p) * 64 + col] = tf32r(v - h);
                        }
                    }
                }
        }

        if (p < PRED - 1) {
            __threadfence();
            __syncthreads();
            if (tid == 0) {
                atomicAdd(&d_psync, 1u);
                unsigned target = (unsigned)gridDim.x * (unsigned)(p + 1);
                unsigned v;
                do {
                    asm volatile("ld.acquire.gpu.u32 %0, [%1];"
                                 : "=r"(v) : "l"(&d_psync));
                    if (v < target) __nanosleep(64);
                } while (v < target);
            }
            __syncthreads();
            __threadfence();
        }
    }
}

// ---------------------------------------------------------------------------
extern "C" void kernel_launch(void* const* d_in, const int* in_sizes, int n_in,
                              void* d_out, int out_size)
{
    const float* em    = (const float*)d_in[0];
    const float* tm    = (const float*)d_in[1];
    const float* initd = (const float*)d_in[2];
    const float* means = (const float*)d_in[3];
    const float* cchol = (const float*)d_in[4];
    const float* W     = (const float*)d_in[5];
    float* out = (float*)d_out;

    cudaFuncSetAttribute(gemm_elp, cudaFuncAttributeMaxDynamicSharedMemorySize,
                         GSMEM_BYTES);
    cudaFuncSetAttribute(pred_em, cudaFuncAttributeMaxDynamicSharedMemorySize,
                         PSMEM_BYTES);
    cudaFuncSetAttribute(pred_rec_persist, cudaFuncAttributeMaxDynamicSharedMemorySize,
                         PSMEM_BYTES);

    prep_small<<<1, 32>>>(tm, initd);                           // 1
    prep_chol<<<8, 256>>>(cchol, means);                        // 2
    wp2_kernel<<<dim3(64, 8), 256>>>(W);                        // 3
    gemm_elp<<<dim3(256, 8), 256, GSMEM_BYTES>>>(em);           // 4 <- ncu slot
    forward_kernel<<<16, 32>>>();                               // 5
    wsplit_kernel<<<2048, 256>>>(W);                            // 6
    win_init_kernel<<<512, 256>>>(em);                          // 7
    group_kernel<<<1, 512>>>();                                 // 8
    pred_em<<<dim3(128, 16), 256, PSMEM_BYTES>>>();             // 9
    pred_rec_persist<<<128, 256, PSMEM_BYTES>>>(means, out);    // 10
}

// round 14
// speedup vs baseline: 1.5748x; 1.1316x over previous
#include <cuda_runtime.h>
#include <cuda_bf16.h>
#include <math.h>
#include <stdint.h>

// ---------------------------------------------------------------------------
// LinearAutoregressiveHMM — round 14:
//  * pred path (pred_em + pred_rec_persist) switched tf32 3-term m16n8k8 ->
//    bf16 hi/lo 3-term m16n8k16: MMA+LDS halved, smem halved, W-split and
//    window arrays now bf16 (half the HBM traffic in wsplit/win_init).
//  * elp GEMM kept from r13 (bf16 k16, 365us measured).
// ---------------------------------------------------------------------------

#define K_ST   8
#define LSEQ   64
#define CDIM   64
#define BATCH  512
#define PRED   16
#define FDIM   4096
#define BST    72            // bf16 smem row stride (144 B)
#define PBST   72            // pred bf16 smem row stride

// static scratch
__device__ __nv_bfloat16 d_Wnb[K_ST * CDIM * FDIM];   // bf16(-(IC@W))
__device__ __nv_bfloat16 d_ICb[K_ST * CDIM * CDIM];   // bf16(IC)
__device__ float d_IC  [K_ST * CDIM * CDIM];
__device__ float d_mp  [K_ST * CDIM];
__device__ float d_logdet[K_ST];
__device__ float d_lt  [K_ST * K_ST];
__device__ float d_linit[K_ST];
__device__ int   d_next[K_ST];
__device__ float d_elp [BATCH * LSEQ * K_ST];
__device__ int   d_states[BATCH * PRED];
__device__ __nv_bfloat16 d_Wbh[K_ST * CDIM * FDIM];   // bf16 hi of W
__device__ __nv_bfloat16 d_Wbl[K_ST * CDIM * FDIM];   // bf16 lo of W
__device__ __nv_bfloat16 d_winbh[BATCH * 80 * CDIM];  // window hi
__device__ __nv_bfloat16 d_winbl[BATCH * 80 * CDIM];  // window lo
__device__ int   d_perm[BATCH];
__device__ int   d_goff[K_ST];
__device__ int   d_gcnt[K_ST];
__device__ int   d_chain[K_ST * PRED];
__device__ float d_yem[BATCH * PRED * CDIM];
__device__ unsigned int d_psync;

// ---------------------------------------------------------------------------
__device__ __forceinline__ uint32_t smem_u32(const void* p) {
    uint32_t a;
    asm("{ .reg .u64 t; cvta.to.shared.u64 t, %1; cvt.u32.u64 %0, t; }"
        : "=r"(a) : "l"(p));
    return a;
}
__device__ __forceinline__ void cpa16(uint32_t dst, const void* src) {
    asm volatile("cp.async.cg.shared.global [%0], [%1], 16;" :: "r"(dst), "l"(src));
}
#define CP_COMMIT() asm volatile("cp.async.commit_group;" ::: "memory")
#define CP_WAIT1()  asm volatile("cp.async.wait_group 1;" ::: "memory")
#define CP_WAIT0()  asm volatile("cp.async.wait_group 0;" ::: "memory")

__device__ __forceinline__ void mma16b(float c[4], const uint32_t a[4],
                                       uint32_t b0, uint32_t b1) {
    asm volatile(
        "mma.sync.aligned.m16n8k16.row.col.f32.bf16.bf16.f32 "
        "{%0,%1,%2,%3},{%4,%5,%6,%7},{%8,%9},{%0,%1,%2,%3};"
        : "+f"(c[0]), "+f"(c[1]), "+f"(c[2]), "+f"(c[3])
        : "r"(a[0]), "r"(a[1]), "r"(a[2]), "r"(a[3]), "r"(b0), "r"(b1));
}

// ---------------------------------------------------------------------------
__global__ void prep_small(const float* __restrict__ tm,
                           const float* __restrict__ initd)
{
    int tid = threadIdx.x;
    if (tid < K_ST) {
        float row[K_ST];
        float m = -1e30f;
        for (int j = 0; j < K_ST; ++j) { row[j] = tm[tid * K_ST + j]; m = fmaxf(m, row[j]); }
        float s = 0.f;
        for (int j = 0; j < K_ST; ++j) s += expf(row[j] - m);
        float lse = m + logf(s);
        for (int j = 0; j < K_ST; ++j)
            d_lt[tid * K_ST + j] = logf(expf(row[j] - lse) + 1e-8f);
        int arg = 0; float best = row[0];
        for (int j = 1; j < K_ST; ++j) if (row[j] > best) { best = row[j]; arg = j; }
        d_next[tid] = arg;
    }
    if (tid == 8) {
        float m = -1e30f;
        for (int j = 0; j < K_ST; ++j) m = fmaxf(m, initd[j]);
        float s = 0.f;
        for (int j = 0; j < K_ST; ++j) s += expf(initd[j] - m);
        float lse = m + logf(s);
        for (int j = 0; j < K_ST; ++j) d_linit[j] = initd[j] - lse;
    }
}

// ---------------------------------------------------------------------------
__global__ void prep_chol(const float* __restrict__ cchol,
                          const float* __restrict__ means)
{
    __shared__ float T[CDIM * CDIM];
    __shared__ float Cv[CDIM * CDIM];
    int tid = threadIdx.x;
    int k = blockIdx.x;

    for (int idx = tid; idx < CDIM * CDIM; idx += 256) {
        int i = idx >> 6, j = idx & 63;
        float v = cchol[k * CDIM * CDIM + idx];
        T[idx] = (j > i) ? 0.f : (j == i ? expf(v) : v);
    }
    __syncthreads();
    for (int idx = tid; idx < CDIM * CDIM; idx += 256) {
        int i = idx >> 6, j = idx & 63;
        int mmax = (i < j) ? i : j;
        float s = (i == j) ? 1e-6f : 0.f;
        for (int m = 0; m <= mmax; ++m) s += T[i * 64 + m] * T[j * 64 + m];
        Cv[idx] = s;
    }
    __syncthreads();
    for (int c = 0; c < CDIM; ++c) {
        if (tid == 0) Cv[c * 64 + c] = sqrtf(Cv[c * 64 + c]);
        __syncthreads();
        float dinv = 1.f / Cv[c * 64 + c];
        for (int i = c + 1 + tid; i < CDIM; i += 256) Cv[i * 64 + c] *= dinv;
        __syncthreads();
        for (int idx = tid; idx < CDIM * CDIM; idx += 256) {
            int i = idx >> 6, m = idx & 63;
            if (i > c && m > c && m <= i)
                Cv[i * 64 + m] -= Cv[i * 64 + c] * Cv[m * 64 + c];
        }
        __syncthreads();
    }
    if (tid == 0) {
        float s = 0.f;
        for (int i = 0; i < CDIM; ++i) s += logf(Cv[i * 64 + i]);
        d_logdet[k] = s;
    }
    for (int idx = tid; idx < CDIM * CDIM; idx += 256) T[idx] = 0.f;
    __syncthreads();
    if (tid < CDIM) {
        int c = tid;
        T[c * 64 + c] = 1.f / Cv[c * 64 + c];
        for (int i = c + 1; i < CDIM; ++i) {
            float s = 0.f;
            for (int m = c; m < i; ++m) s += Cv[i * 64 + m] * T[m * 64 + c];
            T[i * 64 + c] = -s / Cv[i * 64 + i];
        }
    }
    __syncthreads();
    for (int idx = tid; idx < CDIM * CDIM; idx += 256) {
        float v = T[idx];
        d_IC[k * CDIM * CDIM + idx] = v;
        d_ICb[k * CDIM * CDIM + idx] = __float2bfloat16_rn(v);
    }
    if (tid < CDIM) {
        float s = 0.f;
        for (int j = 0; j < CDIM; ++j) s += T[tid * 64 + j] * means[k * CDIM + j];
        d_mp[k * CDIM + tid] = s;
    }
}

// ---------------------------------------------------------------------------
__global__ __launch_bounds__(256) void wp2_kernel(const float* __restrict__ W)
{
    __shared__ float Wt[64 * 65];
    __shared__ float ICs[64 * 65];
    int f0 = blockIdx.x * 64, k = blockIdx.y;
    int tid = threadIdx.x;

    for (int idx = tid; idx < 4096; idx += 256) {
        int c = idx >> 6, c2 = idx & 63;
        ICs[c * 65 + c2] = d_IC[k * 4096 + c * 64 + c2];
        Wt[c * 65 + c2] = W[(size_t)k * CDIM * FDIM + c * FDIM + f0 + c2];
    }
    __syncthreads();

    int fi = tid & 63, cq = tid >> 6;
    #pragma unroll 4
    for (int t = 0; t < 16; ++t) {
        int c = cq * 16 + t;
        float s = 0.f;
        #pragma unroll 16
        for (int c2 = 0; c2 < 64; ++c2)
            s += ICs[c * 65 + c2] * Wt[c2 * 65 + fi];
        d_Wnb[((size_t)(k * 64 + c)) * FDIM + f0 + fi] = __float2bfloat16_rn(-s);
    }
}

// ---------------------------------------------------------------------------
// bf16 hi/lo split of W for the prediction loop
// ---------------------------------------------------------------------------
__global__ void wsplit_kernel(const float* __restrict__ W)
{
    int i = blockIdx.x * 1024 + threadIdx.x * 4;
    #pragma unroll
    for (int j = 0; j < 4; ++j) {
        float v = W[i + j];
        __nv_bfloat16 h = __float2bfloat16_rn(v);
        d_Wbh[i + j] = h;
        d_Wbl[i + j] = __float2bfloat16_rn(v - __bfloat162float(h));
    }
}

__global__ void win_init_kernel(const float* __restrict__ em)
{
    int b = blockIdx.x;
    for (int i = threadIdx.x; i < FDIM; i += 256) {
        float v = em[(size_t)b * FDIM + i];
        __nv_bfloat16 h = __float2bfloat16_rn(v);
        d_winbh[(size_t)b * 5120 + i] = h;
        d_winbl[(size_t)b * 5120 + i] = __float2bfloat16_rn(v - __bfloat162float(h));
    }
}

// ---------------------------------------------------------------------------
// elp GEMM, bf16 m16n8k16 (unchanged from r13).
// ---------------------------------------------------------------------------
#define GA_HALF   (128 * BST)
#define GB_STAGE  (64 * BST)
#define GSMEM_BYTES ((2 * GA_HALF + 2 * GB_STAGE) * 2)

extern __shared__ float smf[];

__device__ __forceinline__ void g_fill_B(int l, int stage, int k,
                                         uint32_t sb, int tid)
{
    uint32_t base = sb + (2 * GA_HALF + stage * GB_STAGE) * 2;
    for (int idx = tid; idx < 512; idx += 256) {
        int n = idx >> 3, q = idx & 7;
        const __nv_bfloat16* src = (l < 64)
            ? d_Wnb + ((size_t)(k * 64 + n)) * FDIM + l * 64 + q * 8
            : d_ICb + (k * 64 + n) * 64 + q * 8;
        cpa16(base + n * (BST * 2) + q * 16, src);
    }
    CP_COMMIT();
}

__global__ __launch_bounds__(256) void gemm_elp(const float* __restrict__ em)
{
    uint32_t sb = smem_u32(smf);
    __nv_bfloat16* smb = (__nv_bfloat16*)smf;
    int tid = threadIdx.x;
    int wid = tid >> 5, lane = tid & 31;
    int g = lane >> 2, q4 = lane & 3;
    int bx = blockIdx.x, k = blockIdx.y;
    int b0 = bx * 2;

    g_fill_B(0, 0, k, sb, tid);

    for (int idx = tid; idx < 2 * 64 * 9; idx += 256) {
        int b = idx / (64 * 9); int rem = idx - b * 64 * 9;
        int r = rem / 9, q = rem - r * 9;
        *(uint4*)((char*)(smb + b * GA_HALF + r * BST) + q * 16) =
            make_uint4(0, 0, 0, 0);
    }
    for (int idx = tid; idx < 2048; idx += 256) {
        int b = idx >> 10; int t = (idx >> 4) & 63; int q = idx & 15;
        float4 v = *(const float4*)(em + (((size_t)(b0 + b)) * 64 + t) * 64 + q * 4);
        uint32_t w0 = (uint32_t)__bfloat16_as_ushort(__float2bfloat16_rn(v.x)) |
                      ((uint32_t)__bfloat16_as_ushort(__float2bfloat16_rn(v.y)) << 16);
        uint32_t w1 = (uint32_t)__bfloat16_as_ushort(__float2bfloat16_rn(v.z)) |
                      ((uint32_t)__bfloat16_as_ushort(__float2bfloat16_rn(v.w)) << 16);
        *(uint2*)(smb + b * GA_HALF + (64 + t) * BST + q * 4) = make_uint2(w0, w1);
    }

    int warpM = wid >> 1, warpN = wid & 1;
    int bp = warpM >> 1;
    int tb = (warpM & 1) * 32;
    const __nv_bfloat16* Ab = smb + bp * GA_HALF;

    float C[2][4][4];
    #pragma unroll
    for (int mt = 0; mt < 2; ++mt)
        #pragma unroll
        for (int nt = 0; nt < 4; ++nt)
            #pragma unroll
            for (int i = 0; i < 4; ++i) C[mt][nt][i] = 0.f;

    for (int l = 0; l <= 64; ++l) {
        int s = l & 1;
        if (l < 64) { g_fill_B(l + 1, s ^ 1, k, sb, tid); CP_WAIT1(); }
        else        { CP_WAIT0(); }
        __syncthreads();

        bool act0 = (l + tb) >= 49;
        bool act1 = (l + tb) >= 33;
        if (act1) {
            const __nv_bfloat16* Bs = smb + 2 * GA_HALF + s * GB_STAGE;
            int fbase = tb + l + g;
            #pragma unroll
            for (int st = 0; st < 4; ++st) {
                int c2 = st * 16 + 2 * q4;
                uint32_t A1[4];
                {
                    const __nv_bfloat16* ar = Ab + (fbase + 16) * BST + c2;
                    A1[0] = *(const uint32_t*)ar;
                    A1[1] = *(const uint32_t*)(ar + 8 * BST);
                    A1[2] = *(const uint32_t*)(ar + 8);
                    A1[3] = *(const uint32_t*)(ar + 8 * BST + 8);
                }
                uint32_t A0[4];
                if (act0) {
                    const __nv_bfloat16* ar = Ab + fbase * BST + c2;
                    A0[0] = *(const uint32_t*)ar;
                    A0[1] = *(const uint32_t*)(ar + 8 * BST);
                    A0[2] = *(const uint32_t*)(ar + 8);
                    A0[3] = *(const uint32_t*)(ar + 8 * BST + 8);
                }
                #pragma unroll
                for (int nt = 0; nt < 4; ++nt) {
                    int n = warpN * 32 + nt * 8 + g;
                    uint32_t bv0 = *(const uint32_t*)(Bs + n * BST + c2);
                    uint32_t bv1 = *(const uint32_t*)(Bs + n * BST + c2 + 8);
                    if (act0) mma16b(C[0][nt], A0, bv0, bv1);
                    mma16b(C[1][nt], A1, bv0, bv1);
                }
            }
        }
        __syncthreads();
    }

    float* qsm = (float*)(smb + 2 * GA_HALF);
    float ldk = d_logdet[k];
    const float* mpk = d_mp + k * CDIM;

    #pragma unroll
    for (int mt = 0; mt < 2; ++mt) {
        #pragma unroll
        for (int rh = 0; rh < 2; ++rh) {
            float sum = 0.f;
            #pragma unroll
            for (int nt = 0; nt < 4; ++nt) {
                int col = warpN * 32 + nt * 8 + q4 * 2;
                float v0 = C[mt][nt][rh * 2 + 0] - mpk[col];
                float v1 = C[mt][nt][rh * 2 + 1] - mpk[col + 1];
                sum += v0 * v0 + v1 * v1;
            }
            sum += __shfl_xor_sync(0xffffffffu, sum, 1);
            sum += __shfl_xor_sync(0xffffffffu, sum, 2);
            if (q4 == 0) {
                int m = warpM * 32 + mt * 16 + rh * 8 + g;
                qsm[m * 2 + warpN] = sum;
            }
        }
    }
    __syncthreads();
    if (tid < 128) {
        int m = tid;
        float quad = qsm[m * 2] + qsm[m * 2 + 1];
        int b = b0 + (m >= 64), t = m & 63;
        const float C_LOG2PI = 64.f * 1.8378770664093453f;
        d_elp[(((size_t)b) * 64 + t) * 8 + k] = -0.5f * (C_LOG2PI + quad) - ldk;
    }
}

// ---------------------------------------------------------------------------
__global__ void forward_kernel()
{
    __shared__ float lt_s[K_ST * K_ST];
    int tid = threadIdx.x;
    for (int i = tid; i < K_ST * K_ST; i += 32) lt_s[i] = d_lt[i];
    __syncthreads();
    int b = blockIdx.x * 32 + tid;
    if (b >= BATCH) return;

    const float* e = d_elp + (size_t)b * LSEQ * K_ST;
    float la[K_ST];
    for (int k = 0; k < K_ST; ++k) la[k] = d_linit[k] + e[k];
    for (int t = 1; t < LSEQ; ++t) {
        const float* et = e + t * K_ST;
        float nla[K_ST];
        #pragma unroll
        for (int k = 0; k < K_ST; ++k) {
            float m = -1e30f;
            #pragma unroll
            for (int j = 0; j < K_ST; ++j) m = fmaxf(m, la[j] + lt_s[j * K_ST + k]);
            float s = 0.f;
            #pragma unroll
            for (int j = 0; j < K_ST; ++j) s += __expf(la[j] + lt_s[j * K_ST + k] - m);
            nla[k] = m + __logf(s) + et[k];
        }
        #pragma unroll
        for (int k = 0; k < K_ST; ++k) la[k] = nla[k];
    }
    int arg = 0; float best = la[0];
    for (int k = 1; k < K_ST; ++k) if (la[k] > best) { best = la[k]; arg = k; }
    int s = d_next[arg];
    for (int p = 0; p < PRED; ++p) { d_states[b * PRED + p] = s; s = d_next[s]; }
}

// ---------------------------------------------------------------------------
__global__ void group_kernel()
{
    __shared__ int cnt[K_ST], off[K_ST + 1], cur[K_ST];
    int tid = threadIdx.x;
    if (tid == 0) d_psync = 0u;
    if (tid < K_ST) { cnt[tid] = 0; cur[tid] = 0; }
    __syncthreads();
    int g = d_states[tid * PRED];
    atomicAdd(&cnt[g], 1);
    __syncthreads();
    if (tid == 0) {
        off[0] = 0;
        for (int i = 0; i < K_ST; ++i) off[i + 1] = off[i] + cnt[i];
    }
    __syncthreads();
    int pos = off[g] + atomicAdd(&cur[g], 1);
    d_perm[pos] = tid;
    if (tid < K_ST) {
        d_gcnt[tid] = cnt[tid];
        d_goff[tid] = off[tid];
        int s = tid;
        for (int p = 0; p < PRED; ++p) { d_chain[tid * PRED + p] = s; s = d_next[s]; }
    }
}

// ---------------------------------------------------------------------------
// pred path: bf16 hi/lo 3-term, m16n8k16.
// A: 2 parts x 32 rows x PBST bf16; B: 2 parts x 64 rows x PBST, 2 stages.
// ---------------------------------------------------------------------------
#define PA_E      (2 * 2 * 32 * PBST)   // 9216 bf16
#define PB_STAGE_E (2 * 64 * PBST)      // 9216 bf16
#define PSMEM_BYTES ((PA_E + 2 * PB_STAGE_E) * 2)   // 55296

__device__ __forceinline__ void p_fill2(int aframe, int bchunk, int stage, int k,
                                        int goff, int cnt, int row0,
                                        uint32_t sb, int tid)
{
    for (int idx = tid; idx < 512; idx += 256) {
        int part = idx >> 8, i = (idx >> 3) & 31, q = idx & 7;
        int r = row0 + i; if (r >= cnt) r = row0;
        int b = d_perm[goff + r];
        const __nv_bfloat16* base = part ? d_winbl : d_winbh;
        const __nv_bfloat16* src = base + ((size_t)b * 80 + aframe) * 64 + q * 8;
        cpa16(sb + (stage * (2 * 32 * PBST) + part * (32 * PBST) + i * PBST + q * 8) * 2, src);
    }
    for (int idx = tid; idx < 1024; idx += 256) {
        int part = idx >> 9, n = (idx >> 3) & 63, q = idx & 7;
        const __nv_bfloat16* base = part ? d_Wbl : d_Wbh;
        const __nv_bfloat16* src = base + ((size_t)(k * 64 + n)) * FDIM + bchunk * 64 + q * 8;
        cpa16(sb + (PA_E + stage * PB_STAGE_E + part * (64 * PBST) + n * PBST + q * 8) * 2, src);
    }
    CP_COMMIT();
}

__device__ __forceinline__ void p_mma(float C[2][4], int s, int warpM, int warpN,
                                      int gg, int q4)
{
    const __nv_bfloat16* smb = (const __nv_bfloat16*)smf;
    const __nv_bfloat16* Ah = smb + s * (2 * 32 * PBST);
    const __nv_bfloat16* Al = Ah + 32 * PBST;
    const __nv_bfloat16* Bh = smb + PA_E + s * PB_STAGE_E;
    const __nv_bfloat16* Bl = Bh + 64 * PBST;
    int r0 = warpM * 16 + gg;

    #pragma unroll
    for (int st = 0; st < 4; ++st) {
        int c2 = st * 16 + 2 * q4;
        uint32_t ah[4], al[4];
        {
            const __nv_bfloat16* ar = Ah + r0 * PBST + c2;
            ah[0] = *(const uint32_t*)ar;
            ah[1] = *(const uint32_t*)(ar + 8 * PBST);
            ah[2] = *(const uint32_t*)(ar + 8);
            ah[3] = *(const uint32_t*)(ar + 8 * PBST + 8);
        }
        {
            const __nv_bfloat16* ar = Al + r0 * PBST + c2;
            al[0] = *(const uint32_t*)ar;
            al[1] = *(const uint32_t*)(ar + 8 * PBST);
            al[2] = *(const uint32_t*)(ar + 8);
            al[3] = *(const uint32_t*)(ar + 8 * PBST + 8);
        }
        #pragma unroll
        for (int nt = 0; nt < 2; ++nt) {
            int n = warpN * 16 + nt * 8 + gg;
            uint32_t bh0 = *(const uint32_t*)(Bh + n * PBST + c2);
            uint32_t bh1 = *(const uint32_t*)(Bh + n * PBST + c2 + 8);
            uint32_t bl0 = *(const uint32_t*)(Bl + n * PBST + c2);
            uint32_t bl1 = *(const uint32_t*)(Bl + n * PBST + c2 + 8);
            mma16b(C[nt], ah, bh0, bh1);
            mma16b(C[nt], ah, bl0, bl1);
            mma16b(C[nt], al, bh0, bh1);
        }
    }
}

__global__ __launch_bounds__(256) void pred_em()
{
    int p = blockIdx.y;
    int g = blockIdx.x >> 4, tile = blockIdx.x & 15;
    int cnt = d_gcnt[g];
    int row0 = tile * 32;
    if (row0 >= cnt) return;
    int goff = d_goff[g];
    int k = d_chain[g * PRED + p];

    uint32_t sb = smem_u32(smf);
    int tid = threadIdx.x;
    int wid = tid >> 5, lane = tid & 31;
    int gg = lane >> 2, q4 = lane & 3;
    int warpM = wid >> 2, warpN = wid & 3;

    float C[2][4];
    #pragma unroll
    for (int nt = 0; nt < 2; ++nt)
        #pragma unroll
        for (int i = 0; i < 4; ++i) C[nt][i] = 0.f;

    int nchunks = 64 - p;
    p_fill2(p, 0, 0, k, goff, cnt, row0, sb, tid);
    for (int j = 0; j < nchunks; ++j) {
        int s = j & 1;
        if (j < nchunks - 1) {
            p_fill2(p + j + 1, j + 1, s ^ 1, k, goff, cnt, row0, sb, tid);
            CP_WAIT1();
        } else CP_WAIT0();
        __syncthreads();
        p_mma(C, s, warpM, warpN, gg, q4);
        __syncthreads();
    }

    #pragma unroll
    for (int nt = 0; nt < 2; ++nt)
        #pragma unroll
        for (int rh = 0; rh < 2; ++rh) {
            int m = warpM * 16 + rh * 8 + gg;
            int r = row0 + m;
            if (r < cnt) {
                int b = d_perm[goff + r];
                #pragma unroll
                for (int cc = 0; cc < 2; ++cc) {
                    int col = warpN * 16 + nt * 8 + q4 * 2 + cc;
                    d_yem[((size_t)b * PRED + p) * CDIM + col] = C[nt][rh * 2 + cc];
                }
            }
        }
}

// ---------------------------------------------------------------------------
__global__ __launch_bounds__(256, 2) void pred_rec_persist(
    const float* __restrict__ means, float* __restrict__ out)
{
    int bid = blockIdx.x;
    int g = bid >> 4, tile = bid & 15;
    int goff = d_goff[g];
    int cnt = d_gcnt[g];
    int row0 = tile * 32;
    bool active = (row0 < cnt);

    uint32_t sb = smem_u32(smf);
    int tid = threadIdx.x;
    int wid = tid >> 5, lane = tid & 31;
    int gg = lane >> 2, q4 = lane & 3;
    int warpM = wid >> 2, warpN = wid & 3;

    for (int p = 0; p < PRED; ++p) {
        int k = d_chain[g * PRED + p];

        float C[2][4];
        #pragma unroll
        for (int nt = 0; nt < 2; ++nt)
            #pragma unroll
            for (int i = 0; i < 4; ++i) C[nt][i] = 0.f;

        if (active && p > 0) {
            p_fill2(64, 64 - p, 0, k, goff, cnt, row0, sb, tid);
            for (int q = 0; q < p; ++q) {
                int s = q & 1;
                if (q < p - 1) {
                    p_fill2(64 + q + 1, 64 - p + q + 1, s ^ 1, k, goff, cnt, row0, sb, tid);
                    CP_WAIT1();
                } else CP_WAIT0();
                __syncthreads();
                p_mma(C, s, warpM, warpN, gg, q4);
                __syncthreads();
            }
        }

        if (active) {
            #pragma unroll
            for (int nt = 0; nt < 2; ++nt)
                #pragma unroll
                for (int rh = 0; rh < 2; ++rh) {
                    int m = warpM * 16 + rh * 8 + gg;
                    int r = row0 + m;
                    if (r < cnt) {
                        int b = d_perm[goff + r];
                        #pragma unroll
                        for (int cc = 0; cc < 2; ++cc) {
                            int col = warpN * 16 + nt * 8 + q4 * 2 + cc;
                            float v = C[nt][rh * 2 + cc]
                                    + d_yem[((size_t)b * PRED + p) * CDIM + col]
                                    + means[k * CDIM + col];
                            out[((size_t)b * PRED + p) * CDIM + col] = v;
                            __nv_bfloat16 h = __float2bfloat16_rn(v);
                            d_winbh[((size_t)b * 80 + 64 + p) * 64 + col] = h;
                            d_winbl[((size_t)b * 80 + 64 + p) * 64 + col] =
                                __float2bfloat16_rn(v - __bfloat162float(h));
                        }
                    }
                }
        }

        if (p < PRED - 1) {
            __threadfence();
            __syncthreads();
            if (tid == 0) {
                atomicAdd(&d_psync, 1u);
                unsigned target = (unsigned)gridDim.x * (unsigned)(p + 1);
                unsigned v;
                do {
                    asm volatile("ld.acquire.gpu.u32 %0, [%1];"
                                 : "=r"(v) : "l"(&d_psync));
                    if (v < target) __nanosleep(64);
                } while (v < target);
            }
            __syncthreads();
            __threadfence();
        }
    }
}

// ---------------------------------------------------------------------------
extern "C" void kernel_launch(void* const* d_in, const int* in_sizes, int n_in,
                              void* d_out, int out_size)
{
    const float* em    = (const float*)d_in[0];
    const float* tm    = (const float*)d_in[1];
    const float* initd = (const float*)d_in[2];
    const float* means = (const float*)d_in[3];
    const float* cchol = (const float*)d_in[4];
    const float* W     = (const float*)d_in[5];
    float* out = (float*)d_out;

    cudaFuncSetAttribute(gemm_elp, cudaFuncAttributeMaxDynamicSharedMemorySize,
                         GSMEM_BYTES);
    cudaFuncSetAttribute(pred_em, cudaFuncAttributeMaxDynamicSharedMemorySize,
                         PSMEM_BYTES);
    cudaFuncSetAttribute(pred_rec_persist, cudaFuncAttributeMaxDynamicSharedMemorySize,
                         PSMEM_BYTES);

    prep_small<<<1, 32>>>(tm, initd);                           // 1
    prep_chol<<<8, 256>>>(cchol, means);                        // 2
    wp2_kernel<<<dim3(64, 8), 256>>>(W);                        // 3
    gemm_elp<<<dim3(256, 8), 256, GSMEM_BYTES>>>(em);           // 4 <- ncu slot
    forward_kernel<<<16, 32>>>();                               // 5
    wsplit_kernel<<<2048, 256>>>(W);                            // 6
    win_init_kernel<<<512, 256>>>(em);                          // 7
    group_kernel<<<1, 512>>>();                                 // 8
    pred_em<<<dim3(128, 16), 256, PSMEM_BYTES>>>();             // 9
    pred_rec_persist<<<128, 256, PSMEM_BYTES>>>(means, out);    // 10
}

// round 15
// speedup vs baseline: 1.6178x; 1.0273x over previous
#include <cuda_runtime.h>
#include <cuda_bf16.h>
#include <math.h>
#include <stdint.h>

// ---------------------------------------------------------------------------
// LinearAutoregressiveHMM — round 15:
//  * gemm_elp fragment loads -> ldmatrix.m8n8.x4.b16 (A and B): per-chunk
//    shared-load instruction count drops 48-64 -> 12-16. Addresses affine in
//    the Toeplitz chunk index (one add per chunk).
//  * everything else verbatim from r14 (bf16 elp + bf16-split pred).
// ---------------------------------------------------------------------------

#define K_ST   8
#define LSEQ   64
#define CDIM   64
#define BATCH  512
#define PRED   16
#define FDIM   4096
#define BST    72            // bf16 smem row stride (144 B) — ldmatrix conflict-free
#define PBST   72

// static scratch
__device__ __nv_bfloat16 d_Wnb[K_ST * CDIM * FDIM];
__device__ __nv_bfloat16 d_ICb[K_ST * CDIM * CDIM];
__device__ float d_IC  [K_ST * CDIM * CDIM];
__device__ float d_mp  [K_ST * CDIM];
__device__ float d_logdet[K_ST];
__device__ float d_lt  [K_ST * K_ST];
__device__ float d_linit[K_ST];
__device__ int   d_next[K_ST];
__device__ float d_elp [BATCH * LSEQ * K_ST];
__device__ int   d_states[BATCH * PRED];
__device__ __nv_bfloat16 d_Wbh[K_ST * CDIM * FDIM];
__device__ __nv_bfloat16 d_Wbl[K_ST * CDIM * FDIM];
__device__ __nv_bfloat16 d_winbh[BATCH * 80 * CDIM];
__device__ __nv_bfloat16 d_winbl[BATCH * 80 * CDIM];
__device__ int   d_perm[BATCH];
__device__ int   d_goff[K_ST];
__device__ int   d_gcnt[K_ST];
__device__ int   d_chain[K_ST * PRED];
__device__ float d_yem[BATCH * PRED * CDIM];
__device__ unsigned int d_psync;

// ---------------------------------------------------------------------------
__device__ __forceinline__ uint32_t smem_u32(const void* p) {
    uint32_t a;
    asm("{ .reg .u64 t; cvta.to.shared.u64 t, %1; cvt.u32.u64 %0, t; }"
        : "=r"(a) : "l"(p));
    return a;
}
__device__ __forceinline__ void cpa16(uint32_t dst, const void* src) {
    asm volatile("cp.async.cg.shared.global [%0], [%1], 16;" :: "r"(dst), "l"(src));
}
#define CP_COMMIT() asm volatile("cp.async.commit_group;" ::: "memory")
#define CP_WAIT1()  asm volatile("cp.async.wait_group 1;" ::: "memory")
#define CP_WAIT0()  asm volatile("cp.async.wait_group 0;" ::: "memory")

__device__ __forceinline__ void mma16b(float c[4], const uint32_t a[4],
                                       uint32_t b0, uint32_t b1) {
    asm volatile(
        "mma.sync.aligned.m16n8k16.row.col.f32.bf16.bf16.f32 "
        "{%0,%1,%2,%3},{%4,%5,%6,%7},{%8,%9},{%0,%1,%2,%3};"
        : "+f"(c[0]), "+f"(c[1]), "+f"(c[2]), "+f"(c[3])
        : "r"(a[0]), "r"(a[1]), "r"(a[2]), "r"(a[3]), "r"(b0), "r"(b1));
}
__device__ __forceinline__ void ldsm4(uint32_t r[4], uint32_t addr) {
    asm volatile("ldmatrix.sync.aligned.m8n8.x4.shared.b16 {%0,%1,%2,%3}, [%4];"
        : "=r"(r[0]), "=r"(r[1]), "=r"(r[2]), "=r"(r[3]) : "r"(addr));
}

// ---------------------------------------------------------------------------
__global__ void prep_small(const float* __restrict__ tm,
                           const float* __restrict__ initd)
{
    int tid = threadIdx.x;
    if (tid < K_ST) {
        float row[K_ST];
        float m = -1e30f;
        for (int j = 0; j < K_ST; ++j) { row[j] = tm[tid * K_ST + j]; m = fmaxf(m, row[j]); }
        float s = 0.f;
        for (int j = 0; j < K_ST; ++j) s += expf(row[j] - m);
        float lse = m + logf(s);
        for (int j = 0; j < K_ST; ++j)
            d_lt[tid * K_ST + j] = logf(expf(row[j] - lse) + 1e-8f);
        int arg = 0; float best = row[0];
        for (int j = 1; j < K_ST; ++j) if (row[j] > best) { best = row[j]; arg = j; }
        d_next[tid] = arg;
    }
    if (tid == 8) {
        float m = -1e30f;
        for (int j = 0; j < K_ST; ++j) m = fmaxf(m, initd[j]);
        float s = 0.f;
        for (int j = 0; j < K_ST; ++j) s += expf(initd[j] - m);
        float lse = m + logf(s);
        for (int j = 0; j < K_ST; ++j) d_linit[j] = initd[j] - lse;
    }
}

// ---------------------------------------------------------------------------
__global__ void prep_chol(const float* __restrict__ cchol,
                          const float* __restrict__ means)
{
    __shared__ float T[CDIM * CDIM];
    __shared__ float Cv[CDIM * CDIM];
    int tid = threadIdx.x;
    int k = blockIdx.x;

    for (int idx = tid; idx < CDIM * CDIM; idx += 256) {
        int i = idx >> 6, j = idx & 63;
        float v = cchol[k * CDIM * CDIM + idx];
        T[idx] = (j > i) ? 0.f : (j == i ? expf(v) : v);
    }
    __syncthreads();
    for (int idx = tid; idx < CDIM * CDIM; idx += 256) {
        int i = idx >> 6, j = idx & 63;
        int mmax = (i < j) ? i : j;
        float s = (i == j) ? 1e-6f : 0.f;
        for (int m = 0; m <= mmax; ++m) s += T[i * 64 + m] * T[j * 64 + m];
        Cv[idx] = s;
    }
    __syncthreads();
    for (int c = 0; c < CDIM; ++c) {
        if (tid == 0) Cv[c * 64 + c] = sqrtf(Cv[c * 64 + c]);
        __syncthreads();
        float dinv = 1.f / Cv[c * 64 + c];
        for (int i = c + 1 + tid; i < CDIM; i += 256) Cv[i * 64 + c] *= dinv;
        __syncthreads();
        for (int idx = tid; idx < CDIM * CDIM; idx += 256) {
            int i = idx >> 6, m = idx & 63;
            if (i > c && m > c && m <= i)
                Cv[i * 64 + m] -= Cv[i * 64 + c] * Cv[m * 64 + c];
        }
        __syncthreads();
    }
    if (tid == 0) {
        float s = 0.f;
        for (int i = 0; i < CDIM; ++i) s += logf(Cv[i * 64 + i]);
        d_logdet[k] = s;
    }
    for (int idx = tid; idx < CDIM * CDIM; idx += 256) T[idx] = 0.f;
    __syncthreads();
    if (tid < CDIM) {
        int c = tid;
        T[c * 64 + c] = 1.f / Cv[c * 64 + c];
        for (int i = c + 1; i < CDIM; ++i) {
            float s = 0.f;
            for (int m = c; m < i; ++m) s += Cv[i * 64 + m] * T[m * 64 + c];
            T[i * 64 + c] = -s / Cv[i * 64 + i];
        }
    }
    __syncthreads();
    for (int idx = tid; idx < CDIM * CDIM; idx += 256) {
        float v = T[idx];
        d_IC[k * CDIM * CDIM + idx] = v;
        d_ICb[k * CDIM * CDIM + idx] = __float2bfloat16_rn(v);
    }
    if (tid < CDIM) {
        float s = 0.f;
        for (int j = 0; j < CDIM; ++j) s += T[tid * 64 + j] * means[k * CDIM + j];
        d_mp[k * CDIM + tid] = s;
    }
}

// ---------------------------------------------------------------------------
__global__ __launch_bounds__(256) void wp2_kernel(const float* __restrict__ W)
{
    __shared__ float Wt[64 * 65];
    __shared__ float ICs[64 * 65];
    int f0 = blockIdx.x * 64, k = blockIdx.y;
    int tid = threadIdx.x;

    for (int idx = tid; idx < 4096; idx += 256) {
        int c = idx >> 6, c2 = idx & 63;
        ICs[c * 65 + c2] = d_IC[k * 4096 + c * 64 + c2];
        Wt[c * 65 + c2] = W[(size_t)k * CDIM * FDIM + c * FDIM + f0 + c2];
    }
    __syncthreads();

    int fi = tid & 63, cq = tid >> 6;
    #pragma unroll 4
    for (int t = 0; t < 16; ++t) {
        int c = cq * 16 + t;
        float s = 0.f;
        #pragma unroll 16
        for (int c2 = 0; c2 < 64; ++c2)
            s += ICs[c * 65 + c2] * Wt[c2 * 65 + fi];
        d_Wnb[((size_t)(k * 64 + c)) * FDIM + f0 + fi] = __float2bfloat16_rn(-s);
    }
}

// ---------------------------------------------------------------------------
__global__ void wsplit_kernel(const float* __restrict__ W)
{
    int i = blockIdx.x * 1024 + threadIdx.x * 4;
    #pragma unroll
    for (int j = 0; j < 4; ++j) {
        float v = W[i + j];
        __nv_bfloat16 h = __float2bfloat16_rn(v);
        d_Wbh[i + j] = h;
        d_Wbl[i + j] = __float2bfloat16_rn(v - __bfloat162float(h));
    }
}

__global__ void win_init_kernel(const float* __restrict__ em)
{
    int b = blockIdx.x;
    for (int i = threadIdx.x; i < FDIM; i += 256) {
        float v = em[(size_t)b * FDIM + i];
        __nv_bfloat16 h = __float2bfloat16_rn(v);
        d_winbh[(size_t)b * 5120 + i] = h;
        d_winbl[(size_t)b * 5120 + i] = __float2bfloat16_rn(v - __bfloat162float(h));
    }
}

// ---------------------------------------------------------------------------
// elp GEMM, bf16 m16n8k16 with ldmatrix fragment loads.
// ---------------------------------------------------------------------------
#define GA_HALF   (128 * BST)
#define GB_STAGE  (64 * BST)
#define GSMEM_BYTES ((2 * GA_HALF + 2 * GB_STAGE) * 2)

extern __shared__ float smf[];

__device__ __forceinline__ void g_fill_B(int l, int stage, int k,
                                         uint32_t sb, int tid)
{
    uint32_t base = sb + (2 * GA_HALF + stage * GB_STAGE) * 2;
    for (int idx = tid; idx < 512; idx += 256) {
        int n = idx >> 3, q = idx & 7;
        const __nv_bfloat16* src = (l < 64)
            ? d_Wnb + ((size_t)(k * 64 + n)) * FDIM + l * 64 + q * 8
            : d_ICb + (k * 64 + n) * 64 + q * 8;
        cpa16(base + n * (BST * 2) + q * 16, src);
    }
    CP_COMMIT();
}

__global__ __launch_bounds__(256) void gemm_elp(const float* __restrict__ em)
{
    uint32_t sb = smem_u32(smf);
    __nv_bfloat16* smb = (__nv_bfloat16*)smf;
    int tid = threadIdx.x;
    int wid = tid >> 5, lane = tid & 31;
    int g = lane >> 2, q4 = lane & 3;
    int bx = blockIdx.x, k = blockIdx.y;
    int b0 = bx * 2;

    g_fill_B(0, 0, k, sb, tid);

    // A panel: rows 0..63 zero, rows 64..127 = emissions (bf16)
    for (int idx = tid; idx < 2 * 64 * 9; idx += 256) {
        int b = idx / (64 * 9); int rem = idx - b * 64 * 9;
        int r = rem / 9, q = rem - r * 9;
        *(uint4*)((char*)(smb + b * GA_HALF + r * BST) + q * 16) =
            make_uint4(0, 0, 0, 0);
    }
    for (int idx = tid; idx < 2048; idx += 256) {
        int b = idx >> 10; int t = (idx >> 4) & 63; int q = idx & 15;
        float4 v = *(const float4*)(em + (((size_t)(b0 + b)) * 64 + t) * 64 + q * 4);
        uint32_t w0 = (uint32_t)__bfloat16_as_ushort(__float2bfloat16_rn(v.x)) |
                      ((uint32_t)__bfloat16_as_ushort(__float2bfloat16_rn(v.y)) << 16);
        uint32_t w1 = (uint32_t)__bfloat16_as_ushort(__float2bfloat16_rn(v.z)) |
                      ((uint32_t)__bfloat16_as_ushort(__float2bfloat16_rn(v.w)) << 16);
        *(uint2*)(smb + b * GA_HALF + (64 + t) * BST + q * 4) = make_uint2(w0, w1);
    }

    int warpM = wid >> 1, warpN = wid & 1;
    int bp = warpM >> 1;
    int tb = (warpM & 1) * 32;

    // ldmatrix per-lane address offsets
    int aRow = ((lane >> 3) & 1) * 8 + (lane & 7);   // A: R0/R1 rows, R2/R3 = +k8
    int aCol = (lane >> 4) * 8;
    int bRow = (lane >> 4) * 8 + (lane & 7);          // B: R0/R1 = n-tile even, R2/R3 odd
    int bCol = ((lane >> 3) & 1) * 8;
    // A base (mt=0): row = tb + aRow (+ l per chunk), col aCol
    uint32_t aB0 = sb + ((uint32_t)(bp * GA_HALF) + (uint32_t)(tb + aRow) * BST + aCol) * 2;
    uint32_t aB1 = aB0 + 16 * BST * 2;               // mt=1 (+16 rows)
    uint32_t bBs[2];
    #pragma unroll
    for (int s = 0; s < 2; ++s)
        bBs[s] = sb + ((uint32_t)(2 * GA_HALF + s * GB_STAGE) +
                       (uint32_t)(warpN * 32 + bRow) * BST + bCol) * 2;

    float C[2][4][4];
    #pragma unroll
    for (int mt = 0; mt < 2; ++mt)
        #pragma unroll
        for (int nt = 0; nt < 4; ++nt)
            #pragma unroll
            for (int i = 0; i < 4; ++i) C[mt][nt][i] = 0.f;

    for (int l = 0; l <= 64; ++l) {
        int s = l & 1;
        if (l < 64) { g_fill_B(l + 1, s ^ 1, k, sb, tid); CP_WAIT1(); }
        else        { CP_WAIT0(); }
        __syncthreads();

        bool act0 = (l + tb) >= 49;
        bool act1 = (l + tb) >= 33;
        if (act1) {
            uint32_t aOff = (uint32_t)l * (BST * 2);
            #pragma unroll
            for (int st = 0; st < 4; ++st) {
                uint32_t A1[4];
                ldsm4(A1, aB1 + aOff + st * 32);
                uint32_t A0[4];
                if (act0) ldsm4(A0, aB0 + aOff + st * 32);
                #pragma unroll
                for (int pr = 0; pr < 2; ++pr) {
                    uint32_t Bv[4];
                    ldsm4(Bv, bBs[s] + pr * (16 * BST * 2) + st * 32);
                    mma16b(C[1][pr * 2 + 0], A1, Bv[0], Bv[1]);
                    mma16b(C[1][pr * 2 + 1], A1, Bv[2], Bv[3]);
                    if (act0) {
                        mma16b(C[0][pr * 2 + 0], A0, Bv[0], Bv[1]);
                        mma16b(C[0][pr * 2 + 1], A0, Bv[2], Bv[3]);
                    }
                }
            }
        }
        __syncthreads();
    }

    // epilogue: quad = sum_cols (D - mp)^2 -> elp  (reuse B area)
    float* qsm = (float*)(smb + 2 * GA_HALF);
    float ldk = d_logdet[k];
    const float* mpk = d_mp + k * CDIM;

    #pragma unroll
    for (int mt = 0; mt < 2; ++mt) {
        #pragma unroll
        for (int rh = 0; rh < 2; ++rh) {
            float sum = 0.f;
            #pragma unroll
            for (int nt = 0; nt < 4; ++nt) {
                int col = warpN * 32 + nt * 8 + q4 * 2;
                float v0 = C[mt][nt][rh * 2 + 0] - mpk[col];
                float v1 = C[mt][nt][rh * 2 + 1] - mpk[col + 1];
                sum += v0 * v0 + v1 * v1;
            }
            sum += __shfl_xor_sync(0xffffffffu, sum, 1);
            sum += __shfl_xor_sync(0xffffffffu, sum, 2);
            if (q4 == 0) {
                int m = warpM * 32 + mt * 16 + rh * 8 + g;
                qsm[m * 2 + warpN] = sum;
            }
        }
    }
    __syncthreads();
    if (tid < 128) {
        int m = tid;
        float quad = qsm[m * 2] + qsm[m * 2 + 1];
        int b = b0 + (m >= 64), t = m & 63;
        const float C_LOG2PI = 64.f * 1.8378770664093453f;
        d_elp[(((size_t)b) * 64 + t) * 8 + k] = -0.5f * (C_LOG2PI + quad) - ldk;
    }
}

// ---------------------------------------------------------------------------
__global__ void forward_kernel()
{
    __shared__ float lt_s[K_ST * K_ST];
    int tid = threadIdx.x;
    for (int i = tid; i < K_ST * K_ST; i += 32) lt_s[i] = d_lt[i];
    __syncthreads();
    int b = blockIdx.x * 32 + tid;
    if (b >= BATCH) return;

    const float* e = d_elp + (size_t)b * LSEQ * K_ST;
    float la[K_ST];
    for (int k = 0; k < K_ST; ++k) la[k] = d_linit[k] + e[k];
    for (int t = 1; t < LSEQ; ++t) {
        const float* et = e + t * K_ST;
        float nla[K_ST];
        #pragma unroll
        for (int k = 0; k < K_ST; ++k) {
            float m = -1e30f;
            #pragma unroll
            for (int j = 0; j < K_ST; ++j) m = fmaxf(m, la[j] + lt_s[j * K_ST + k]);
            float s = 0.f;
            #pragma unroll
            for (int j = 0; j < K_ST; ++j) s += __expf(la[j] + lt_s[j * K_ST + k] - m);
            nla[k] = m + __logf(s) + et[k];
        }
        #pragma unroll
        for (int k = 0; k < K_ST; ++k) la[k] = nla[k];
    }
    int arg = 0; float best = la[0];
    for (int k = 1; k < K_ST; ++k) if (la[k] > best) { best = la[k]; arg = k; }
    int s = d_next[arg];
    for (int p = 0; p < PRED; ++p) { d_states[b * PRED + p] = s; s = d_next[s]; }
}

// ---------------------------------------------------------------------------
__global__ void group_kernel()
{
    __shared__ int cnt[K_ST], off[K_ST + 1], cur[K_ST];
    int tid = threadIdx.x;
    if (tid == 0) d_psync = 0u;
    if (tid < K_ST) { cnt[tid] = 0; cur[tid] = 0; }
    __syncthreads();
    int g = d_states[tid * PRED];
    atomicAdd(&cnt[g], 1);
    __syncthreads();
    if (tid == 0) {
        off[0] = 0;
        for (int i = 0; i < K_ST; ++i) off[i + 1] = off[i] + cnt[i];
    }
    __syncthreads();
    int pos = off[g] + atomicAdd(&cur[g], 1);
    d_perm[pos] = tid;
    if (tid < K_ST) {
        d_gcnt[tid] = cnt[tid];
        d_goff[tid] = off[tid];
        int s = tid;
        for (int p = 0; p < PRED; ++p) { d_chain[tid * PRED + p] = s; s = d_next[s]; }
    }
}

// ---------------------------------------------------------------------------
// pred path (bf16 hi/lo 3-term, m16n8k16) — verbatim r14
// ---------------------------------------------------------------------------
#define PA_E      (2 * 2 * 32 * PBST)
#define PB_STAGE_E (2 * 64 * PBST)
#define PSMEM_BYTES ((PA_E + 2 * PB_STAGE_E) * 2)

__device__ __forceinline__ void p_fill2(int aframe, int bchunk, int stage, int k,
                                        int goff, int cnt, int row0,
                                        uint32_t sb, int tid)
{
    for (int idx = tid; idx < 512; idx += 256) {
        int part = idx >> 8, i = (idx >> 3) & 31, q = idx & 7;
        int r = row0 + i; if (r >= cnt) r = row0;
        int b = d_perm[goff + r];
        const __nv_bfloat16* base = part ? d_winbl : d_winbh;
        const __nv_bfloat16* src = base + ((size_t)b * 80 + aframe) * 64 + q * 8;
        cpa16(sb + (stage * (2 * 32 * PBST) + part * (32 * PBST) + i * PBST + q * 8) * 2, src);
    }
    for (int idx = tid; idx < 1024; idx += 256) {
        int part = idx >> 9, n = (idx >> 3) & 63, q = idx & 7;
        const __nv_bfloat16* base = part ? d_Wbl : d_Wbh;
        const __nv_bfloat16* src = base + ((size_t)(k * 64 + n)) * FDIM + bchunk * 64 + q * 8;
        cpa16(sb + (PA_E + stage * PB_STAGE_E + part * (64 * PBST) + n * PBST + q * 8) * 2, src);
    }
    CP_COMMIT();
}

__device__ __forceinline__ void p_mma(float C[2][4], int s, int warpM, int warpN,
                                      int gg, int q4)
{
    const __nv_bfloat16* smb = (const __nv_bfloat16*)smf;
    const __nv_bfloat16* Ah = smb + s * (2 * 32 * PBST);
    const __nv_bfloat16* Al = Ah + 32 * PBST;
    const __nv_bfloat16* Bh = smb + PA_E + s * PB_STAGE_E;
    const __nv_bfloat16* Bl = Bh + 64 * PBST;
    int r0 = warpM * 16 + gg;

    #pragma unroll
    for (int st = 0; st < 4; ++st) {
        int c2 = st * 16 + 2 * q4;
        uint32_t ah[4], al[4];
        {
            const __nv_bfloat16* ar = Ah + r0 * PBST + c2;
            ah[0] = *(const uint32_t*)ar;
            ah[1] = *(const uint32_t*)(ar + 8 * PBST);
            ah[2] = *(const uint32_t*)(ar + 8);
            ah[3] = *(const uint32_t*)(ar + 8 * PBST + 8);
        }
        {
            const __nv_bfloat16* ar = Al + r0 * PBST + c2;
            al[0] = *(const uint32_t*)ar;
            al[1] = *(const uint32_t*)(ar + 8 * PBST);
            al[2] = *(const uint32_t*)(ar + 8);
            al[3] = *(const uint32_t*)(ar + 8 * PBST + 8);
        }
        #pragma unroll
        for (int nt = 0; nt < 2; ++nt) {
            int n = warpN * 16 + nt * 8 + gg;
            uint32_t bh0 = *(const uint32_t*)(Bh + n * PBST + c2);
            uint32_t bh1 = *(const uint32_t*)(Bh + n * PBST + c2 + 8);
            uint32_t bl0 = *(const uint32_t*)(Bl + n * PBST + c2);
            uint32_t bl1 = *(const uint32_t*)(Bl + n * PBST + c2 + 8);
            mma16b(C[nt], ah, bh0, bh1);
            mma16b(C[nt], ah, bl0, bl1);
            mma16b(C[nt], al, bh0, bh1);
        }
    }
}

__global__ __launch_bounds__(256) void pred_em()
{
    int p = blockIdx.y;
    int g = blockIdx.x >> 4, tile = blockIdx.x & 15;
    int cnt = d_gcnt[g];
    int row0 = tile * 32;
    if (row0 >= cnt) return;
    int goff = d_goff[g];
    int k = d_chain[g * PRED + p];

    uint32_t sb = smem_u32(smf);
    int tid = threadIdx.x;
    int wid = tid >> 5, lane = tid & 31;
    int gg = lane >> 2, q4 = lane & 3;
    int warpM = wid >> 2, warpN = wid & 3;

    float C[2][4];
    #pragma unroll
    for (int nt = 0; nt < 2; ++nt)
        #pragma unroll
        for (int i = 0; i < 4; ++i) C[nt][i] = 0.f;

    int nchunks = 64 - p;
    p_fill2(p, 0, 0, k, goff, cnt, row0, sb, tid);
    for (int j = 0; j < nchunks; ++j) {
        int s = j & 1;
        if (j < nchunks - 1) {
            p_fill2(p + j + 1, j + 1, s ^ 1, k, goff, cnt, row0, sb, tid);
            CP_WAIT1();
        } else CP_WAIT0();
        __syncthreads();
        p_mma(C, s, warpM, warpN, gg, q4);
        __syncthreads();
    }

    #pragma unroll
    for (int nt = 0; nt < 2; ++nt)
        #pragma unroll
        for (int rh = 0; rh < 2; ++rh) {
            int m = warpM * 16 + rh * 8 + gg;
            int r = row0 + m;
            if (r < cnt) {
                int b = d_perm[goff + r];
                #pragma unroll
                for (int cc = 0; cc < 2; ++cc) {
                    int col = warpN * 16 + nt * 8 + q4 * 2 + cc;
                    d_yem[((size_t)b * PRED + p) * CDIM + col] = C[nt][rh * 2 + cc];
                }
            }
        }
}

// ---------------------------------------------------------------------------
__global__ __launch_bounds__(256, 2) void pred_rec_persist(
    const float* __restrict__ means, float* __restrict__ out)
{
    int bid = blockIdx.x;
    int g = bid >> 4, tile = bid & 15;
    int goff = d_goff[g];
    int cnt = d_gcnt[g];
    int row0 = tile * 32;
    bool active = (row0 < cnt);

    uint32_t sb = smem_u32(smf);
    int tid = threadIdx.x;
    int wid = tid >> 5, lane = tid & 31;
    int gg = lane >> 2, q4 = lane & 3;
    int warpM = wid >> 2, warpN = wid & 3;

    for (int p = 0; p < PRED; ++p) {
        int k = d_chain[g * PRED + p];

        float C[2][4];
        #pragma unroll
        for (int nt = 0; nt < 2; ++nt)
            #pragma unroll
            for (int i = 0; i < 4; ++i) C[nt][i] = 0.f;

        if (active && p > 0) {
            p_fill2(64, 64 - p, 0, k, goff, cnt, row0, sb, tid);
            for (int q = 0; q < p; ++q) {
                int s = q & 1;
                if (q < p - 1) {
                    p_fill2(64 + q + 1, 64 - p + q + 1, s ^ 1, k, goff, cnt, row0, sb, tid);
                    CP_WAIT1();
                } else CP_WAIT0();
                __syncthreads();
                p_mma(C, s, warpM, warpN, gg, q4);
                __syncthreads();
            }
        }

        if (active) {
            #pragma unroll
            for (int nt = 0; nt < 2; ++nt)
                #pragma unroll
                for (int rh = 0; rh < 2; ++rh) {
                    int m = warpM * 16 + rh * 8 + gg;
                    int r = row0 + m;
                    if (r < cnt) {
                        int b = d_perm[goff + r];
                        #pragma unroll
                        for (int cc = 0; cc < 2; ++cc) {
                            int col = warpN * 16 + nt * 8 + q4 * 2 + cc;
                            float v = C[nt][rh * 2 + cc]
                                    + d_yem[((size_t)b * PRED + p) * CDIM + col]
                                    + means[k * CDIM + col];
                            out[((size_t)b * PRED + p) * CDIM + col] = v;
                            __nv_bfloat16 h = __float2bfloat16_rn(v);
                            d_winbh[((size_t)b * 80 + 64 + p) * 64 + col] = h;
                            d_winbl[((size_t)b * 80 + 64 + p) * 64 + col] =
                                __float2bfloat16_rn(v - __bfloat162float(h));
                        }
                    }
                }
        }

        if (p < PRED - 1) {
            __threadfence();
            __syncthreads();
            if (tid == 0) {
                atomicAdd(&d_psync, 1u);
                unsigned target = (unsigned)gridDim.x * (unsigned)(p + 1);
                unsigned v;
                do {
                    asm volatile("ld.acquire.gpu.u32 %0, [%1];"
                                 : "=r"(v) : "l"(&d_psync));
                    if (v < target) __nanosleep(64);
                } while (v < target);
            }
            __syncthreads();
            __threadfence();
        }
    }
}

// ---------------------------------------------------------------------------
extern "C" void kernel_launch(void* const* d_in, const int* in_sizes, int n_in,
                              void* d_out, int out_size)
{
    const float* em    = (const float*)d_in[0];
    const float* tm    = (const float*)d_in[1];
    const float* initd = (const float*)d_in[2];
    const float* means = (const float*)d_in[3];
    const float* cchol = (const float*)d_in[4];
    const float* W     = (const float*)d_in[5];
    float* out = (float*)d_out;

    cudaFuncSetAttribute(gemm_elp, cudaFuncAttributeMaxDynamicSharedMemorySize,
                         GSMEM_BYTES);
    cudaFuncSetAttribute(pred_em, cudaFuncAttributeMaxDynamicSharedMemorySize,
                         PSMEM_BYTES);
    cudaFuncSetAttribute(pred_rec_persist, cudaFuncAttributeMaxDynamicSharedMemorySize,
                         PSMEM_BYTES);

    prep_small<<<1, 32>>>(tm, initd);                           // 1
    prep_chol<<<8, 256>>>(cchol, means);                        // 2
    wp2_kernel<<<dim3(64, 8), 256>>>(W);                        // 3
    gemm_elp<<<dim3(256, 8), 256, GSMEM_BYTES>>>(em);           // 4 <- ncu slot
    forward_kernel<<<16, 32>>>();                               // 5
    wsplit_kernel<<<2048, 256>>>(W);                            // 6
    win_init_kernel<<<512, 256>>>(em);                          // 7
    group_kernel<<<1, 512>>>();                                 // 8
    pred_em<<<dim3(128, 16), 256, PSMEM_BYTES>>>();             // 9
    pred_rec_persist<<<128, 256, PSMEM_BYTES>>>(means, out);    // 10
}

// round 17
// speedup vs baseline: 1.6801x; 1.0385x over previous
#include <cuda_runtime.h>
#include <cuda_bf16.h>
#include <math.h>
#include <stdint.h>

// ---------------------------------------------------------------------------
// LinearAutoregressiveHMM — round 17 (resubmit of r16 after broker failure):
//  * pred path fragment loads -> ldmatrix (same bit-verified mappings as the
//    r15 gemm): shared-load count per chunk 64 -> 16.
//  * prep_small merged into prep_chol; wsplit+win_init merged -> 8 launches.
//  * gemm_elp verbatim r15 (339us measured).
// ---------------------------------------------------------------------------

#define K_ST   8
#define LSEQ   64
#define CDIM   64
#define BATCH  512
#define PRED   16
#define FDIM   4096
#define BST    72
#define PBST   72

// static scratch
__device__ __nv_bfloat16 d_Wnb[K_ST * CDIM * FDIM];
__device__ __nv_bfloat16 d_ICb[K_ST * CDIM * CDIM];
__device__ float d_IC  [K_ST * CDIM * CDIM];
__device__ float d_mp  [K_ST * CDIM];
__device__ float d_logdet[K_ST];
__device__ float d_lt  [K_ST * K_ST];
__device__ float d_linit[K_ST];
__device__ int   d_next[K_ST];
__device__ float d_elp [BATCH * LSEQ * K_ST];
__device__ int   d_states[BATCH * PRED];
__device__ __nv_bfloat16 d_Wbh[K_ST * CDIM * FDIM];
__device__ __nv_bfloat16 d_Wbl[K_ST * CDIM * FDIM];
__device__ __nv_bfloat16 d_winbh[BATCH * 80 * CDIM];
__device__ __nv_bfloat16 d_winbl[BATCH * 80 * CDIM];
__device__ int   d_perm[BATCH];
__device__ int   d_goff[K_ST];
__device__ int   d_gcnt[K_ST];
__device__ int   d_chain[K_ST * PRED];
__device__ float d_yem[BATCH * PRED * CDIM];
__device__ unsigned int d_psync;

// ---------------------------------------------------------------------------
__device__ __forceinline__ uint32_t smem_u32(const void* p) {
    uint32_t a;
    asm("{ .reg .u64 t; cvta.to.shared.u64 t, %1; cvt.u32.u64 %0, t; }"
        : "=r"(a) : "l"(p));
    return a;
}
__device__ __forceinline__ void cpa16(uint32_t dst, const void* src) {
    asm volatile("cp.async.cg.shared.global [%0], [%1], 16;" :: "r"(dst), "l"(src));
}
#define CP_COMMIT() asm volatile("cp.async.commit_group;" ::: "memory")
#define CP_WAIT1()  asm volatile("cp.async.wait_group 1;" ::: "memory")
#define CP_WAIT0()  asm volatile("cp.async.wait_group 0;" ::: "memory")

__device__ __forceinline__ void mma16b(float c[4], const uint32_t a[4],
                                       uint32_t b0, uint32_t b1) {
    asm volatile(
        "mma.sync.aligned.m16n8k16.row.col.f32.bf16.bf16.f32 "
        "{%0,%1,%2,%3},{%4,%5,%6,%7},{%8,%9},{%0,%1,%2,%3};"
        : "+f"(c[0]), "+f"(c[1]), "+f"(c[2]), "+f"(c[3])
        : "r"(a[0]), "r"(a[1]), "r"(a[2]), "r"(a[3]), "r"(b0), "r"(b1));
}
__device__ __forceinline__ void ldsm4(uint32_t r[4], uint32_t addr) {
    asm volatile("ldmatrix.sync.aligned.m8n8.x4.shared.b16 {%0,%1,%2,%3}, [%4];"
        : "=r"(r[0]), "=r"(r[1]), "=r"(r[2]), "=r"(r[3]) : "r"(addr));
}

// ---------------------------------------------------------------------------
// prep_chol: per-state Cholesky etc; block 0 also does softmax/next tables.
// ---------------------------------------------------------------------------
__global__ void prep_chol(const float* __restrict__ cchol,
                          const float* __restrict__ means,
                          const float* __restrict__ tm,
                          const float* __restrict__ initd)
{
    __shared__ float T[CDIM * CDIM];
    __shared__ float Cv[CDIM * CDIM];
    int tid = threadIdx.x;
    int k = blockIdx.x;

    if (k == 0) {
        if (tid < K_ST) {
            float row[K_ST];
            float m = -1e30f;
            for (int j = 0; j < K_ST; ++j) { row[j] = tm[tid * K_ST + j]; m = fmaxf(m, row[j]); }
            float s = 0.f;
            for (int j = 0; j < K_ST; ++j) s += expf(row[j] - m);
            float lse = m + logf(s);
            for (int j = 0; j < K_ST; ++j)
                d_lt[tid * K_ST + j] = logf(expf(row[j] - lse) + 1e-8f);
            int arg = 0; float best = row[0];
            for (int j = 1; j < K_ST; ++j) if (row[j] > best) { best = row[j]; arg = j; }
            d_next[tid] = arg;
        }
        if (tid == 8) {
            float m = -1e30f;
            for (int j = 0; j < K_ST; ++j) m = fmaxf(m, initd[j]);
            float s = 0.f;
            for (int j = 0; j < K_ST; ++j) s += expf(initd[j] - m);
            float lse = m + logf(s);
            for (int j = 0; j < K_ST; ++j) d_linit[j] = initd[j] - lse;
        }
    }

    for (int idx = tid; idx < CDIM * CDIM; idx += 256) {
        int i = idx >> 6, j = idx & 63;
        float v = cchol[k * CDIM * CDIM + idx];
        T[idx] = (j > i) ? 0.f : (j == i ? expf(v) : v);
    }
    __syncthreads();
    for (int idx = tid; idx < CDIM * CDIM; idx += 256) {
        int i = idx >> 6, j = idx & 63;
        int mmax = (i < j) ? i : j;
        float s = (i == j) ? 1e-6f : 0.f;
        for (int m = 0; m <= mmax; ++m) s += T[i * 64 + m] * T[j * 64 + m];
        Cv[idx] = s;
    }
    __syncthreads();
    for (int c = 0; c < CDIM; ++c) {
        if (tid == 0) Cv[c * 64 + c] = sqrtf(Cv[c * 64 + c]);
        __syncthreads();
        float dinv = 1.f / Cv[c * 64 + c];
        for (int i = c + 1 + tid; i < CDIM; i += 256) Cv[i * 64 + c] *= dinv;
        __syncthreads();
        for (int idx = tid; idx < CDIM * CDIM; idx += 256) {
            int i = idx >> 6, m = idx & 63;
            if (i > c && m > c && m <= i)
                Cv[i * 64 + m] -= Cv[i * 64 + c] * Cv[m * 64 + c];
        }
        __syncthreads();
    }
    if (tid == 0) {
        float s = 0.f;
        for (int i = 0; i < CDIM; ++i) s += logf(Cv[i * 64 + i]);
        d_logdet[k] = s;
    }
    for (int idx = tid; idx < CDIM * CDIM; idx += 256) T[idx] = 0.f;
    __syncthreads();
    if (tid < CDIM) {
        int c = tid;
        T[c * 64 + c] = 1.f / Cv[c * 64 + c];
        for (int i = c + 1; i < CDIM; ++i) {
            float s = 0.f;
            for (int m = c; m < i; ++m) s += Cv[i * 64 + m] * T[m * 64 + c];
            T[i * 64 + c] = -s / Cv[i * 64 + i];
        }
    }
    __syncthreads();
    for (int idx = tid; idx < CDIM * CDIM; idx += 256) {
        float v = T[idx];
        d_IC[k * CDIM * CDIM + idx] = v;
        d_ICb[k * CDIM * CDIM + idx] = __float2bfloat16_rn(v);
    }
    if (tid < CDIM) {
        float s = 0.f;
        for (int j = 0; j < CDIM; ++j) s += T[tid * 64 + j] * means[k * CDIM + j];
        d_mp[k * CDIM + tid] = s;
    }
}

// ---------------------------------------------------------------------------
__global__ __launch_bounds__(256) void wp2_kernel(const float* __restrict__ W)
{
    __shared__ float Wt[64 * 65];
    __shared__ float ICs[64 * 65];
    int f0 = blockIdx.x * 64, k = blockIdx.y;
    int tid = threadIdx.x;

    for (int idx = tid; idx < 4096; idx += 256) {
        int c = idx >> 6, c2 = idx & 63;
        ICs[c * 65 + c2] = d_IC[k * 4096 + c * 64 + c2];
        Wt[c * 65 + c2] = W[(size_t)k * CDIM * FDIM + c * FDIM + f0 + c2];
    }
    __syncthreads();

    int fi = tid & 63, cq = tid >> 6;
    #pragma unroll 4
    for (int t = 0; t < 16; ++t) {
        int c = cq * 16 + t;
        float s = 0.f;
        #pragma unroll 16
        for (int c2 = 0; c2 < 64; ++c2)
            s += ICs[c * 65 + c2] * Wt[c2 * 65 + fi];
        d_Wnb[((size_t)(k * 64 + c)) * FDIM + f0 + fi] = __float2bfloat16_rn(-s);
    }
}

// ---------------------------------------------------------------------------
// merged W bf16-split + window init
// ---------------------------------------------------------------------------
__global__ void split_init_kernel(const float* __restrict__ W,
                                  const float* __restrict__ em)
{
    int bid = blockIdx.x;
    if (bid < 2048) {
        int i = bid * 1024 + threadIdx.x * 4;
        #pragma unroll
        for (int j = 0; j < 4; ++j) {
            float v = W[i + j];
            __nv_bfloat16 h = __float2bfloat16_rn(v);
            d_Wbh[i + j] = h;
            d_Wbl[i + j] = __float2bfloat16_rn(v - __bfloat162float(h));
        }
    } else {
        int b = bid - 2048;
        for (int i = threadIdx.x; i < FDIM; i += 256) {
            float v = em[(size_t)b * FDIM + i];
            __nv_bfloat16 h = __float2bfloat16_rn(v);
            d_winbh[(size_t)b * 5120 + i] = h;
            d_winbl[(size_t)b * 5120 + i] = __float2bfloat16_rn(v - __bfloat162float(h));
        }
    }
}

// ---------------------------------------------------------------------------
// elp GEMM (verbatim r15)
// ---------------------------------------------------------------------------
#define GA_HALF   (128 * BST)
#define GB_STAGE  (64 * BST)
#define GSMEM_BYTES ((2 * GA_HALF + 2 * GB_STAGE) * 2)

extern __shared__ float smf[];

__device__ __forceinline__ void g_fill_B(int l, int stage, int k,
                                         uint32_t sb, int tid)
{
    uint32_t base = sb + (2 * GA_HALF + stage * GB_STAGE) * 2;
    for (int idx = tid; idx < 512; idx += 256) {
        int n = idx >> 3, q = idx & 7;
        const __nv_bfloat16* src = (l < 64)
            ? d_Wnb + ((size_t)(k * 64 + n)) * FDIM + l * 64 + q * 8
            : d_ICb + (k * 64 + n) * 64 + q * 8;
        cpa16(base + n * (BST * 2) + q * 16, src);
    }
    CP_COMMIT();
}

__global__ __launch_bounds__(256) void gemm_elp(const float* __restrict__ em)
{
    uint32_t sb = smem_u32(smf);
    __nv_bfloat16* smb = (__nv_bfloat16*)smf;
    int tid = threadIdx.x;
    int wid = tid >> 5, lane = tid & 31;
    int g = lane >> 2, q4 = lane & 3;
    int bx = blockIdx.x, k = blockIdx.y;
    int b0 = bx * 2;

    g_fill_B(0, 0, k, sb, tid);

    for (int idx = tid; idx < 2 * 64 * 9; idx += 256) {
        int b = idx / (64 * 9); int rem = idx - b * 64 * 9;
        int r = rem / 9, q = rem - r * 9;
        *(uint4*)((char*)(smb + b * GA_HALF + r * BST) + q * 16) =
            make_uint4(0, 0, 0, 0);
    }
    for (int idx = tid; idx < 2048; idx += 256) {
        int b = idx >> 10; int t = (idx >> 4) & 63; int q = idx & 15;
        float4 v = *(const float4*)(em + (((size_t)(b0 + b)) * 64 + t) * 64 + q * 4);
        uint32_t w0 = (uint32_t)__bfloat16_as_ushort(__float2bfloat16_rn(v.x)) |
                      ((uint32_t)__bfloat16_as_ushort(__float2bfloat16_rn(v.y)) << 16);
        uint32_t w1 = (uint32_t)__bfloat16_as_ushort(__float2bfloat16_rn(v.z)) |
                      ((uint32_t)__bfloat16_as_ushort(__float2bfloat16_rn(v.w)) << 16);
        *(uint2*)(smb + b * GA_HALF + (64 + t) * BST + q * 4) = make_uint2(w0, w1);
    }

    int warpM = wid >> 1, warpN = wid & 1;
    int bp = warpM >> 1;
    int tb = (warpM & 1) * 32;

    int aRow = ((lane >> 3) & 1) * 8 + (lane & 7);
    int aCol = (lane >> 4) * 8;
    int bRow = (lane >> 4) * 8 + (lane & 7);
    int bCol = ((lane >> 3) & 1) * 8;
    uint32_t aB0 = sb + ((uint32_t)(bp * GA_HALF) + (uint32_t)(tb + aRow) * BST + aCol) * 2;
    uint32_t aB1 = aB0 + 16 * BST * 2;
    uint32_t bBs[2];
    #pragma unroll
    for (int s = 0; s < 2; ++s)
        bBs[s] = sb + ((uint32_t)(2 * GA_HALF + s * GB_STAGE) +
                       (uint32_t)(warpN * 32 + bRow) * BST + bCol) * 2;

    float C[2][4][4];
    #pragma unroll
    for (int mt = 0; mt < 2; ++mt)
        #pragma unroll
        for (int nt = 0; nt < 4; ++nt)
            #pragma unroll
            for (int i = 0; i < 4; ++i) C[mt][nt][i] = 0.f;

    for (int l = 0; l <= 64; ++l) {
        int s = l & 1;
        if (l < 64) { g_fill_B(l + 1, s ^ 1, k, sb, tid); CP_WAIT1(); }
        else        { CP_WAIT0(); }
        __syncthreads();

        bool act0 = (l + tb) >= 49;
        bool act1 = (l + tb) >= 33;
        if (act1) {
            uint32_t aOff = (uint32_t)l * (BST * 2);
            #pragma unroll
            for (int st = 0; st < 4; ++st) {
                uint32_t A1[4];
                ldsm4(A1, aB1 + aOff + st * 32);
                uint32_t A0[4];
                if (act0) ldsm4(A0, aB0 + aOff + st * 32);
                #pragma unroll
                for (int pr = 0; pr < 2; ++pr) {
                    uint32_t Bv[4];
                    ldsm4(Bv, bBs[s] + pr * (16 * BST * 2) + st * 32);
                    mma16b(C[1][pr * 2 + 0], A1, Bv[0], Bv[1]);
                    mma16b(C[1][pr * 2 + 1], A1, Bv[2], Bv[3]);
                    if (act0) {
                        mma16b(C[0][pr * 2 + 0], A0, Bv[0], Bv[1]);
                        mma16b(C[0][pr * 2 + 1], A0, Bv[2], Bv[3]);
                    }
                }
            }
        }
        __syncthreads();
    }

    float* qsm = (float*)(smb + 2 * GA_HALF);
    float ldk = d_logdet[k];
    const float* mpk = d_mp + k * CDIM;

    #pragma unroll
    for (int mt = 0; mt < 2; ++mt) {
        #pragma unroll
        for (int rh = 0; rh < 2; ++rh) {
            float sum = 0.f;
            #pragma unroll
            for (int nt = 0; nt < 4; ++nt) {
                int col = warpN * 32 + nt * 8 + q4 * 2;
                float v0 = C[mt][nt][rh * 2 + 0] - mpk[col];
                float v1 = C[mt][nt][rh * 2 + 1] - mpk[col + 1];
                sum += v0 * v0 + v1 * v1;
            }
            sum += __shfl_xor_sync(0xffffffffu, sum, 1);
            sum += __shfl_xor_sync(0xffffffffu, sum, 2);
            if (q4 == 0) {
                int m = warpM * 32 + mt * 16 + rh * 8 + g;
                qsm[m * 2 + warpN] = sum;
            }
        }
    }
    __syncthreads();
    if (tid < 128) {
        int m = tid;
        float quad = qsm[m * 2] + qsm[m * 2 + 1];
        int b = b0 + (m >= 64), t = m & 63;
        const float C_LOG2PI = 64.f * 1.8378770664093453f;
        d_elp[(((size_t)b) * 64 + t) * 8 + k] = -0.5f * (C_LOG2PI + quad) - ldk;
    }
}

// ---------------------------------------------------------------------------
__global__ void forward_kernel()
{
    __shared__ float lt_s[K_ST * K_ST];
    int tid = threadIdx.x;
    for (int i = tid; i < K_ST * K_ST; i += 32) lt_s[i] = d_lt[i];
    __syncthreads();
    int b = blockIdx.x * 32 + tid;
    if (b >= BATCH) return;

    const float* e = d_elp + (size_t)b * LSEQ * K_ST;
    float la[K_ST];
    for (int k = 0; k < K_ST; ++k) la[k] = d_linit[k] + e[k];
    for (int t = 1; t < LSEQ; ++t) {
        const float* et = e + t * K_ST;
        float nla[K_ST];
        #pragma unroll
        for (int k = 0; k < K_ST; ++k) {
            float m = -1e30f;
            #pragma unroll
            for (int j = 0; j < K_ST; ++j) m = fmaxf(m, la[j] + lt_s[j * K_ST + k]);
            float s = 0.f;
            #pragma unroll
            for (int j = 0; j < K_ST; ++j) s += __expf(la[j] + lt_s[j * K_ST + k] - m);
            nla[k] = m + __logf(s) + et[k];
        }
        #pragma unroll
        for (int k = 0; k < K_ST; ++k) la[k] = nla[k];
    }
    int arg = 0; float best = la[0];
    for (int k = 1; k < K_ST; ++k) if (la[k] > best) { best = la[k]; arg = k; }
    int s = d_next[arg];
    for (int p = 0; p < PRED; ++p) { d_states[b * PRED + p] = s; s = d_next[s]; }
}

// ---------------------------------------------------------------------------
__global__ void group_kernel()
{
    __shared__ int cnt[K_ST], off[K_ST + 1], cur[K_ST];
    int tid = threadIdx.x;
    if (tid == 0) d_psync = 0u;
    if (tid < K_ST) { cnt[tid] = 0; cur[tid] = 0; }
    __syncthreads();
    int g = d_states[tid * PRED];
    atomicAdd(&cnt[g], 1);
    __syncthreads();
    if (tid == 0) {
        off[0] = 0;
        for (int i = 0; i < K_ST; ++i) off[i + 1] = off[i] + cnt[i];
    }
    __syncthreads();
    int pos = off[g] + atomicAdd(&cur[g], 1);
    d_perm[pos] = tid;
    if (tid < K_ST) {
        d_gcnt[tid] = cnt[tid];
        d_goff[tid] = off[tid];
        int s = tid;
        for (int p = 0; p < PRED; ++p) { d_chain[tid * PRED + p] = s; s = d_next[s]; }
    }
}

// ---------------------------------------------------------------------------
// pred path: bf16 hi/lo 3-term, m16n8k16, ldmatrix fragment loads.
// ---------------------------------------------------------------------------
#define PA_E      (2 * 2 * 32 * PBST)
#define PB_STAGE_E (2 * 64 * PBST)
#define PSMEM_BYTES ((PA_E + 2 * PB_STAGE_E) * 2)

__device__ __forceinline__ void p_fill2(int aframe, int bchunk, int stage, int k,
                                        int goff, int cnt, int row0,
                                        uint32_t sb, int tid)
{
    for (int idx = tid; idx < 512; idx += 256) {
        int part = idx >> 8, i = (idx >> 3) & 31, q = idx & 7;
        int r = row0 + i; if (r >= cnt) r = row0;
        int b = d_perm[goff + r];
        const __nv_bfloat16* base = part ? d_winbl : d_winbh;
        const __nv_bfloat16* src = base + ((size_t)b * 80 + aframe) * 64 + q * 8;
        cpa16(sb + (stage * (2 * 32 * PBST) + part * (32 * PBST) + i * PBST + q * 8) * 2, src);
    }
    for (int idx = tid; idx < 1024; idx += 256) {
        int part = idx >> 9, n = (idx >> 3) & 63, q = idx & 7;
        const __nv_bfloat16* base = part ? d_Wbl : d_Wbh;
        const __nv_bfloat16* src = base + ((size_t)(k * 64 + n)) * FDIM + bchunk * 64 + q * 8;
        cpa16(sb + (PA_E + stage * PB_STAGE_E + part * (64 * PBST) + n * PBST + q * 8) * 2, src);
    }
    CP_COMMIT();
}

// ldmatrix-based MMA body. Al = Ah + 32*PBST*2 bytes; Bl = Bh + 64*PBST*2.
__device__ __forceinline__ void p_mma(float C[2][4], uint32_t aAddr, uint32_t bAddr)
{
    #pragma unroll
    for (int st = 0; st < 4; ++st) {
        uint32_t Ah[4], Al[4], Bh[4], Bl[4];
        ldsm4(Ah, aAddr + st * 32);
        ldsm4(Al, aAddr + st * 32 + 32 * PBST * 2);
        ldsm4(Bh, bAddr + st * 32);
        ldsm4(Bl, bAddr + st * 32 + 64 * PBST * 2);
        #pragma unroll
        for (int nt = 0; nt < 2; ++nt) {
            mma16b(C[nt], Ah, Bh[nt * 2], Bh[nt * 2 + 1]);
            mma16b(C[nt], Ah, Bl[nt * 2], Bl[nt * 2 + 1]);
            mma16b(C[nt], Al, Bh[nt * 2], Bh[nt * 2 + 1]);
        }
    }
}

__global__ __launch_bounds__(256) void pred_em()
{
    int p = blockIdx.y;
    int g = blockIdx.x >> 4, tile = blockIdx.x & 15;
    int cnt = d_gcnt[g];
    int row0 = tile * 32;
    if (row0 >= cnt) return;
    int goff = d_goff[g];
    int k = d_chain[g * PRED + p];

    uint32_t sb = smem_u32(smf);
    int tid = threadIdx.x;
    int wid = tid >> 5, lane = tid & 31;
    int gg = lane >> 2, q4 = lane & 3;
    int warpM = wid >> 2, warpN = wid & 3;

    int aRow = ((lane >> 3) & 1) * 8 + (lane & 7);
    int aCol = (lane >> 4) * 8;
    int bRow = (lane >> 4) * 8 + (lane & 7);
    int bCol = ((lane >> 3) & 1) * 8;
    uint32_t aBs[2], bBs[2];
    #pragma unroll
    for (int s = 0; s < 2; ++s) {
        aBs[s] = sb + ((uint32_t)(s * (2 * 32 * PBST)) +
                       (uint32_t)(warpM * 16 + aRow) * PBST + aCol) * 2;
        bBs[s] = sb + ((uint32_t)(PA_E + s * PB_STAGE_E) +
                       (uint32_t)(warpN * 16 + bRow) * PBST + bCol) * 2;
    }

    float C[2][4];
    #pragma unroll
    for (int nt = 0; nt < 2; ++nt)
        #pragma unroll
        for (int i = 0; i < 4; ++i) C[nt][i] = 0.f;

    int nchunks = 64 - p;
    p_fill2(p, 0, 0, k, goff, cnt, row0, sb, tid);
    for (int j = 0; j < nchunks; ++j) {
        int s = j & 1;
        if (j < nchunks - 1) {
            p_fill2(p + j + 1, j + 1, s ^ 1, k, goff, cnt, row0, sb, tid);
            CP_WAIT1();
        } else CP_WAIT0();
        __syncthreads();
        p_mma(C, aBs[s], bBs[s]);
        __syncthreads();
    }

    #pragma unroll
    for (int nt = 0; nt < 2; ++nt)
        #pragma unroll
        for (int rh = 0; rh < 2; ++rh) {
            int m = warpM * 16 + rh * 8 + gg;
            int r = row0 + m;
            if (r < cnt) {
                int b = d_perm[goff + r];
                #pragma unroll
                for (int cc = 0; cc < 2; ++cc) {
                    int col = warpN * 16 + nt * 8 + q4 * 2 + cc;
                    d_yem[((size_t)b * PRED + p) * CDIM + col] = C[nt][rh * 2 + cc];
                }
            }
        }
}

// ---------------------------------------------------------------------------
__global__ __launch_bounds__(256, 2) void pred_rec_persist(
    const float* __restrict__ means, float* __restrict__ out)
{
    int bid = blockIdx.x;
    int g = bid >> 4, tile = bid & 15;
    int goff = d_goff[g];
    int cnt = d_gcnt[g];
    int row0 = tile * 32;
    bool active = (row0 < cnt);

    uint32_t sb = smem_u32(smf);
    int tid = threadIdx.x;
    int wid = tid >> 5, lane = tid & 31;
    int gg = lane >> 2, q4 = lane & 3;
    int warpM = wid >> 2, warpN = wid & 3;

    int aRow = ((lane >> 3) & 1) * 8 + (lane & 7);
    int aCol = (lane >> 4) * 8;
    int bRow = (lane >> 4) * 8 + (lane & 7);
    int bCol = ((lane >> 3) & 1) * 8;
    uint32_t aBs[2], bBs[2];
    #pragma unroll
    for (int s = 0; s < 2; ++s) {
        aBs[s] = sb + ((uint32_t)(s * (2 * 32 * PBST)) +
                       (uint32_t)(warpM * 16 + aRow) * PBST + aCol) * 2;
        bBs[s] = sb + ((uint32_t)(PA_E + s * PB_STAGE_E) +
                       (uint32_t)(warpN * 16 + bRow) * PBST + bCol) * 2;
    }

    for (int p = 0; p < PRED; ++p) {
        int k = d_chain[g * PRED + p];

        float C[2][4];
        #pragma unroll
        for (int nt = 0; nt < 2; ++nt)
            #pragma unroll
            for (int i = 0; i < 4; ++i) C[nt][i] = 0.f;

        if (active && p > 0) {
            p_fill2(64, 64 - p, 0, k, goff, cnt, row0, sb, tid);
            for (int q = 0; q < p; ++q) {
                int s = q & 1;
                if (q < p - 1) {
                    p_fill2(64 + q + 1, 64 - p + q + 1, s ^ 1, k, goff, cnt, row0, sb, tid);
                    CP_WAIT1();
                } else CP_WAIT0();
                __syncthreads();
                p_mma(C, aBs[s], bBs[s]);
                __syncthreads();
            }
        }

        if (active) {
            #pragma unroll
            for (int nt = 0; nt < 2; ++nt)
                #pragma unroll
                for (int rh = 0; rh < 2; ++rh) {
                    int m = warpM * 16 + rh * 8 + gg;
                    int r = row0 + m;
                    if (r < cnt) {
                        int b = d_perm[goff + r];
                        #pragma unroll
                        for (int cc = 0; cc < 2; ++cc) {
                            int col = warpN * 16 + nt * 8 + q4 * 2 + cc;
                            float v = C[nt][rh * 2 + cc]
                                    + d_yem[((size_t)b * PRED + p) * CDIM + col]
                                    + means[k * CDIM + col];
                            out[((size_t)b * PRED + p) * CDIM + col] = v;
                            __nv_bfloat16 h = __float2bfloat16_rn(v);
                            d_winbh[((size_t)b * 80 + 64 + p) * 64 + col] = h;
                            d_winbl[((size_t)b * 80 + 64 + p) * 64 + col] =
                                __float2bfloat16_rn(v - __bfloat162float(h));
                        }
                    }
                }
        }

        if (p < PRED - 1) {
            __threadfence();
            __syncthreads();
            if (tid == 0) {
                atomicAdd(&d_psync, 1u);
                unsigned target = (unsigned)gridDim.x * (unsigned)(p + 1);
                unsigned v;
                do {
                    asm volatile("ld.acquire.gpu.u32 %0, [%1];"
                                 : "=r"(v) : "l"(&d_psync));
                    if (v < target) __nanosleep(64);
                } while (v < target);
            }
            __syncthreads();
            __threadfence();
        }
    }
}

// ---------------------------------------------------------------------------
extern "C" void kernel_launch(void* const* d_in, const int* in_sizes, int n_in,
                              void* d_out, int out_size)
{
    const float* em    = (const float*)d_in[0];
    const float* tm    = (const float*)d_in[1];
    const float* initd = (const float*)d_in[2];
    const float* means = (const float*)d_in[3];
    const float* cchol = (const float*)d_in[4];
    const float* W     = (const float*)d_in[5];
    float* out = (float*)d_out;

    cudaFuncSetAttribute(gemm_elp, cudaFuncAttributeMaxDynamicSharedMemorySize,
                         GSMEM_BYTES);
    cudaFuncSetAttribute(pred_em, cudaFuncAttributeMaxDynamicSharedMemorySize,
                         PSMEM_BYTES);
    cudaFuncSetAttribute(pred_rec_persist, cudaFuncAttributeMaxDynamicSharedMemorySize,
                         PSMEM_BYTES);

    prep_chol<<<8, 256>>>(cchol, means, tm, initd);             // 1
    wp2_kernel<<<dim3(64, 8), 256>>>(W);                        // 2
    split_init_kernel<<<2560, 256>>>(W, em);                    // 3
    gemm_elp<<<dim3(256, 8), 256, GSMEM_BYTES>>>(em);           // 4 <- ncu slot
    forward_kernel<<<16, 32>>>();                               // 5
    group_kernel<<<1, 512>>>();                                 // 6
    pred_em<<<dim3(128, 16), 256, PSMEM_BYTES>>>();             // 7
    pred_rec_persist<<<128, 256, PSMEM_BYTES>>>(means, out);    // 8
}